// round 13
// baseline (speedup 1.0000x reference)
#include <cuda_runtime.h>
#include <cuda_bf16.h>
#include <cuda_fp16.h>
#include <cstdint>

#define BATCH   16
#define SEQ     256
#define EMBED   512
#define HIDDEN  1024
#define GATES   (4 * HIDDEN)
#define VOCAB   32000
#define MROWS   (BATCH * SEQ)
#define NBLK    128
typedef unsigned long long ull;

// ------------------------- scratch (device globals) -------------------------
__device__ float g_gatesx[MROWS * GATES];
__device__ __nv_bfloat16 g_ah[MROWS * HIDDEN];        // A-history hi (bf16) or fp16 single
__device__ __nv_bfloat16 g_al[MROWS * HIDDEN];        // A-history lo (bf16)
__device__ __nv_bfloat16 g_wh[(size_t)VOCAB * HIDDEN];
__device__ __nv_bfloat16 g_wl[(size_t)VOCAB * HIDDEN];
__device__ __nv_bfloat16 g_whh_h[GATES * HIDDEN];
__device__ __nv_bfloat16 g_whh_l[GATES * HIDDEN];
__device__ __nv_bfloat16 g_hbfh[2][BATCH * HIDDEN];   // recurrent h, bf16 hi
__device__ __nv_bfloat16 g_hbfl[2][BATCH * HIDDEN];   // recurrent h, bf16 lo
__device__ unsigned g_cnt;
__device__ volatile unsigned g_gen;

// ------------------------- HMMA / smem helpers (plain sm_103-safe) ----------
__device__ __forceinline__ uint32_t smem_u32(const void* p) {
    uint32_t a;
    asm("{ .reg .u64 t; cvta.to.shared.u64 t, %1; cvt.u32.u64 %0, t; }" : "=r"(a) : "l"(p));
    return a;
}
__device__ __forceinline__ void mma_bf16(float* d, const unsigned* a, const unsigned* b) {
    asm volatile("mma.sync.aligned.m16n8k16.row.col.f32.bf16.bf16.f32 "
        "{%0,%1,%2,%3}, {%4,%5,%6,%7}, {%8,%9}, {%0,%1,%2,%3};"
        : "+f"(d[0]), "+f"(d[1]), "+f"(d[2]), "+f"(d[3])
        : "r"(a[0]), "r"(a[1]), "r"(a[2]), "r"(a[3]), "r"(b[0]), "r"(b[1]));
}
__device__ __forceinline__ void mma_f16h(float* d, const unsigned* a, const unsigned* b) {
    asm volatile("mma.sync.aligned.m16n8k16.row.col.f32.f16.f16.f32 "
        "{%0,%1,%2,%3}, {%4,%5,%6,%7}, {%8,%9}, {%0,%1,%2,%3};"
        : "+f"(d[0]), "+f"(d[1]), "+f"(d[2]), "+f"(d[3])
        : "r"(a[0]), "r"(a[1]), "r"(a[2]), "r"(a[3]), "r"(b[0]), "r"(b[1]));
}
__device__ __forceinline__ void ldsm_x4(unsigned* r, uint32_t addr) {
    asm volatile("ldmatrix.sync.aligned.m8n8.x4.shared.b16 {%0,%1,%2,%3}, [%4];"
        : "=r"(r[0]), "=r"(r[1]), "=r"(r[2]), "=r"(r[3]) : "r"(addr));
}
__device__ __forceinline__ void cp16(uint32_t dst, const void* src) {
    asm volatile("cp.async.cg.shared.global [%0], [%1], 16;" :: "r"(dst), "l"(src));
}
#define CP_COMMIT()  asm volatile("cp.async.commit_group;" ::: "memory")
#define CP_WAIT(n)   asm volatile("cp.async.wait_group %0;" :: "n"(n) : "memory")
#define SW128(o) ((o) ^ (((o) >> 3) & 0x70))

// ------------------------- flat grid barrier (proven fastest) ---------------
__device__ __forceinline__ void grid_bar(unsigned target) {
    __threadfence();
    __syncthreads();
    if (threadIdx.x == 0) {
        unsigned arr = atomicAdd(&g_cnt, 1u);
        if (arr == NBLK - 1) { g_cnt = 0; __threadfence(); g_gen = target; }
        else { while ((int)(g_gen - target) < 0) {} __threadfence(); }
    }
    __syncthreads();
}

// ------------------------- fp32 -> bf16 hi/lo split -------------------------
__device__ __forceinline__ void split8(float4 v0, float4 v1, uint4& hi, uint4& lo) {
    float f[8] = {v0.x, v0.y, v0.z, v0.w, v1.x, v1.y, v1.z, v1.w};
    unsigned short h[8], l[8];
#pragma unroll
    for (int i = 0; i < 8; i++) {
        __nv_bfloat16 bh = __float2bfloat16_rn(f[i]);
        __nv_bfloat16 bl = __float2bfloat16_rn(f[i] - __bfloat162float(bh));
        h[i] = __bfloat16_as_ushort(bh); l[i] = __bfloat16_as_ushort(bl);
    }
    hi = make_uint4(h[0]|((uint32_t)h[1]<<16), h[2]|((uint32_t)h[3]<<16),
                    h[4]|((uint32_t)h[5]<<16), h[6]|((uint32_t)h[7]<<16));
    lo = make_uint4(l[0]|((uint32_t)l[1]<<16), l[2]|((uint32_t)l[3]<<16),
                    l[4]|((uint32_t)l[5]<<16), l[6]|((uint32_t)l[7]<<16));
}

__global__ void cvt_hilo(const float* __restrict__ src,
                         __nv_bfloat16* __restrict__ hi,
                         __nv_bfloat16* __restrict__ lo, int n8) {
    int i = blockIdx.x * 256 + threadIdx.x;
    if (i >= n8) return;
    const float4* s = (const float4*)src + 2 * (size_t)i;
    uint4 h, l; split8(s[0], s[1], h, l);
    ((uint4*)hi)[i] = h; ((uint4*)lo)[i] = l;
}

// fp32 -> fp16 (single) for the FC weights
__global__ void cvt_f16(const float* __restrict__ src, __half* __restrict__ dst, int n8) {
    int i = blockIdx.x * 256 + threadIdx.x;
    if (i >= n8) return;
    const float4* s = (const float4*)src + 2 * (size_t)i;
    float4 v0 = s[0], v1 = s[1];
    __half2 p0 = __floats2half2_rn(v0.x, v0.y);
    __half2 p1 = __floats2half2_rn(v0.z, v0.w);
    __half2 p2 = __floats2half2_rn(v1.x, v1.y);
    __half2 p3 = __floats2half2_rn(v1.z, v1.w);
    uint4 o;
    o.x = *(unsigned*)&p0; o.y = *(unsigned*)&p1;
    o.z = *(unsigned*)&p2; o.w = *(unsigned*)&p3;
    ((uint4*)dst)[i] = o;
}

__global__ void embed_cvt(const int* __restrict__ x, const float* __restrict__ emb,
                          __nv_bfloat16* __restrict__ hi, __nv_bfloat16* __restrict__ lo) {
    int idx = blockIdx.x * 256 + threadIdx.x;
    int row = idx >> 6;
    int e8  = idx & 63;
    const float4* s = (const float4*)(emb + ((size_t)x[row] << 9)) + 2 * e8;
    uint4 h, l; split8(s[0], s[1], h, l);
    ((uint4*)hi)[idx] = h; ((uint4*)lo)[idx] = l;
}

// ------------------------- HMMA GEMM 3-term bf16 (verified R8) --------------
__device__ __forceinline__ void gemm_load_chunk(
    const __nv_bfloat16* Ah, const __nv_bfloat16* Al,
    const __nv_bfloat16* Bh, const __nv_bfloat16* Bl,
    int m0, int n0, int K, int c, uint32_t sbase, int tid) {
    uint32_t sb = sbase + (c & 1) * 65536;
    int kb = c << 6;
#pragma unroll
    for (int it = 0; it < 4; it++) {
        int idx = it * 256 + tid;
        int row = idx >> 3, cc = idx & 7;
        uint32_t dst = SW128((uint32_t)(row * 128 + cc * 16));
        size_t ga = (size_t)(m0 + row) * K + kb + cc * 8;
        size_t gb = (size_t)(n0 + row) * K + kb + cc * 8;
        cp16(sb + dst,         Ah + ga);
        cp16(sb + 16384 + dst, Al + ga);
        cp16(sb + 32768 + dst, Bh + gb);
        cp16(sb + 49152 + dst, Bl + gb);
    }
    CP_COMMIT();
}

__global__ __launch_bounds__(256)
void hmma_gemm(const __nv_bfloat16* __restrict__ Ah, const __nv_bfloat16* __restrict__ Al,
               const __nv_bfloat16* __restrict__ Bh, const __nv_bfloat16* __restrict__ Bl,
               const float* __restrict__ b1, const float* __restrict__ b2,
               float* __restrict__ C, int N, int K) {
    extern __shared__ char dsm[];
    uint32_t raw = smem_u32(dsm);
    uint32_t sbase = (raw + 1023) & ~1023u;

    int tid = threadIdx.x, wid = tid >> 5, lane = tid & 31;
    int m0 = blockIdx.x << 7, n0 = blockIdx.y << 7;
    int NC = K >> 6;

    gemm_load_chunk(Ah, Al, Bh, Bl, m0, n0, K, 0, sbase, tid);
    gemm_load_chunk(Ah, Al, Bh, Bl, m0, n0, K, 1, sbase, tid);

    int wm = wid >> 2, wn = wid & 3;
    int mb = wm * 64, nb = wn * 32;

    float acc[4][4][4];
#pragma unroll
    for (int i = 0; i < 4; i++)
#pragma unroll
        for (int j = 0; j < 4; j++)
#pragma unroll
            for (int q = 0; q < 4; q++) acc[i][j][q] = 0.f;

    int a_r = mb + (lane & 15);
    int a_cb = lane >> 4;
    int b_r = nb + (lane & 7) + ((lane >> 4) << 3);
    int b_cb = (lane >> 3) & 1;

    for (int c = 0; c < NC; c++) {
        if (c + 1 < NC) { CP_WAIT(1); } else { CP_WAIT(0); }
        __syncthreads();
        uint32_t sb = sbase + (c & 1) * 65536;
#pragma unroll
        for (int kt = 0; kt < 4; kt++) {
            unsigned ah[4][4], al[4][4], bh[2][4], bl[2][4];
#pragma unroll
            for (int mt = 0; mt < 4; mt++) {
                int r = a_r + mt * 16;
                uint32_t off = (uint32_t)(r * 128)
                             + ((((uint32_t)(kt * 2 + a_cb)) ^ ((uint32_t)r & 7)) << 4);
                ldsm_x4(ah[mt], sb + off);
                ldsm_x4(al[mt], sb + 16384 + off);
            }
#pragma unroll
            for (int nt2 = 0; nt2 < 2; nt2++) {
                int r = b_r + nt2 * 16;
                uint32_t off = (uint32_t)(r * 128)
                             + ((((uint32_t)(kt * 2 + b_cb)) ^ ((uint32_t)r & 7)) << 4);
                ldsm_x4(bh[nt2], sb + 32768 + off);
                ldsm_x4(bl[nt2], sb + 49152 + off);
            }
#pragma unroll
            for (int mt = 0; mt < 4; mt++)
#pragma unroll
                for (int nt = 0; nt < 4; nt++) {
                    const unsigned* bhp = &bh[nt >> 1][(nt & 1) * 2];
                    const unsigned* blp = &bl[nt >> 1][(nt & 1) * 2];
                    mma_bf16(acc[mt][nt], ah[mt], bhp);
                    mma_bf16(acc[mt][nt], ah[mt], blp);
                    mma_bf16(acc[mt][nt], al[mt], bhp);
                }
        }
        __syncthreads();
        if (c + 2 < NC)
            gemm_load_chunk(Ah, Al, Bh, Bl, m0, n0, K, c + 2, sbase, tid);
    }

    int er = lane >> 2;
    int ec = (lane & 3) << 1;
#pragma unroll
    for (int nt = 0; nt < 4; nt++) {
        int col = n0 + nb + nt * 8 + ec;
        float2 bv = *(const float2*)(b1 + col);
        if (b2) {
            float2 t2 = *(const float2*)(b2 + col);
            bv.x += t2.x; bv.y += t2.y;
        }
#pragma unroll
        for (int mt = 0; mt < 4; mt++) {
            int r0 = m0 + mb + mt * 16 + er;
            *(float2*)(C + (size_t)r0 * N + col) =
                make_float2(acc[mt][nt][0] + bv.x, acc[mt][nt][1] + bv.y);
            *(float2*)(C + (size_t)(r0 + 8) * N + col) =
                make_float2(acc[mt][nt][2] + bv.x, acc[mt][nt][3] + bv.y);
        }
    }
}

// ------------------------- HMMA GEMM single-term fp16 (FC head) -------------
__device__ __forceinline__ void gemm_load_chunk_f16(
    const __half* A, const __half* B,
    int m0, int n0, int K, int c, uint32_t sbase, int tid) {
    uint32_t sb = sbase + (c & 1) * 32768;
    int kb = c << 6;
#pragma unroll
    for (int it = 0; it < 4; it++) {
        int idx = it * 256 + tid;
        int row = idx >> 3, cc = idx & 7;
        uint32_t dst = SW128((uint32_t)(row * 128 + cc * 16));
        cp16(sb + dst,         A + (size_t)(m0 + row) * K + kb + cc * 8);
        cp16(sb + 16384 + dst, B + (size_t)(n0 + row) * K + kb + cc * 8);
    }
    CP_COMMIT();
}

__global__ __launch_bounds__(256)
void hmma_gemm_f16(const __half* __restrict__ A, const __half* __restrict__ B,
                   const float* __restrict__ b1,
                   float* __restrict__ C, int N, int K) {
    extern __shared__ char dsm[];
    uint32_t raw = smem_u32(dsm);
    uint32_t sbase = (raw + 1023) & ~1023u;

    int tid = threadIdx.x, wid = tid >> 5, lane = tid & 31;
    int m0 = blockIdx.x << 7, n0 = blockIdx.y << 7;
    int NC = K >> 6;

    gemm_load_chunk_f16(A, B, m0, n0, K, 0, sbase, tid);
    gemm_load_chunk_f16(A, B, m0, n0, K, 1, sbase, tid);

    int wm = wid >> 2, wn = wid & 3;
    int mb = wm * 64, nb = wn * 32;

    float acc[4][4][4];
#pragma unroll
    for (int i = 0; i < 4; i++)
#pragma unroll
        for (int j = 0; j < 4; j++)
#pragma unroll
            for (int q = 0; q < 4; q++) acc[i][j][q] = 0.f;

    int a_r = mb + (lane & 15);
    int a_cb = lane >> 4;
    int b_r = nb + (lane & 7) + ((lane >> 4) << 3);
    int b_cb = (lane >> 3) & 1;

    for (int c = 0; c < NC; c++) {
        if (c + 1 < NC) { CP_WAIT(1); } else { CP_WAIT(0); }
        __syncthreads();
        uint32_t sb = sbase + (c & 1) * 32768;
#pragma unroll
        for (int kt = 0; kt < 4; kt++) {
            unsigned ah[4][4], bh[2][4];
#pragma unroll
            for (int mt = 0; mt < 4; mt++) {
                int r = a_r + mt * 16;
                uint32_t off = (uint32_t)(r * 128)
                             + ((((uint32_t)(kt * 2 + a_cb)) ^ ((uint32_t)r & 7)) << 4);
                ldsm_x4(ah[mt], sb + off);
            }
#pragma unroll
            for (int nt2 = 0; nt2 < 2; nt2++) {
                int r = b_r + nt2 * 16;
                uint32_t off = (uint32_t)(r * 128)
                             + ((((uint32_t)(kt * 2 + b_cb)) ^ ((uint32_t)r & 7)) << 4);
                ldsm_x4(bh[nt2], sb + 16384 + off);
            }
#pragma unroll
            for (int mt = 0; mt < 4; mt++)
#pragma unroll
                for (int nt = 0; nt < 4; nt++)
                    mma_f16h(acc[mt][nt], ah[mt], &bh[nt >> 1][(nt & 1) * 2]);
        }
        __syncthreads();
        if (c + 2 < NC)
            gemm_load_chunk_f16(A, B, m0, n0, K, c + 2, sbase, tid);
    }

    int er = lane >> 2;
    int ec = (lane & 3) << 1;
#pragma unroll
    for (int nt = 0; nt < 4; nt++) {
        int col = n0 + nb + nt * 8 + ec;
        float2 bv = *(const float2*)(b1 + col);
#pragma unroll
        for (int mt = 0; mt < 4; mt++) {
            int r0 = m0 + mb + mt * 16 + er;
            *(float2*)(C + (size_t)r0 * N + col) =
                make_float2(acc[mt][nt][0] + bv.x, acc[mt][nt][1] + bv.y);
            *(float2*)(C + (size_t)(r0 + 8) * N + col) =
                make_float2(acc[mt][nt][2] + bv.x, acc[mt][nt][3] + bv.y);
        }
    }
}

// ------------------------- persistent LSTM layer (per-warp h fill) ----------
// Warp w reads only h chunks {2w, 2w+1}: it fills exactly those tiles with its
// own cp.async and syncs via wait_group+syncwarp (no block-wide fill sync).
#define L_WH  0
#define L_WL  65536
#define L_HH  131072
#define L_HL  163840
#define L_ST  196608                       // float stage[8][16][33]
#define L_DYN (1024 + 196608 + 16896)

__global__ __launch_bounds__(256)
void lstm_layer(const __nv_bfloat16* __restrict__ Whh_h,
                const __nv_bfloat16* __restrict__ Whh_l,
                const float* __restrict__ gatesx,
                const float* __restrict__ h0l, const float* __restrict__ c0l,
                float* __restrict__ hT, float* __restrict__ cT, int f16hist) {
    extern __shared__ char dsm[];
    __shared__ float c_sm[128];
    __shared__ unsigned base_sh;

    uint32_t raw = smem_u32(dsm);
    uint32_t sbase = (raw + 1023) & ~1023u;
    char* smp = dsm + (sbase - raw);
    float* stage = (float*)(smp + L_ST);

    int tid = threadIdx.x, bid = blockIdx.x;
    int w = tid >> 5, lane = tid & 31;

    if (tid == 0) base_sh = g_gen;
    __syncthreads();
    unsigned tgt = base_sh;

    // ---- W_hh slice load (once per layer) ----
    for (int p = tid * 2; p < tid * 2 + 2; p++) {
        int l = p >> 4, c = p & 15;
        size_t grow = (size_t)((l >> 3) * HIDDEN + bid * 8 + (l & 7)) * HIDDEN + c * 64;
        uint32_t cb = (uint32_t)(c * 4096);
#pragma unroll
        for (int cc = 0; cc < 8; cc++) {
            uint32_t sw = cb + SW128((uint32_t)(l * 128 + cc * 16));
            *(uint4*)(smp + L_WH + sw) = *(const uint4*)(Whh_h + grow + cc * 8);
            *(uint4*)(smp + L_WL + sw) = *(const uint4*)(Whh_l + grow + cc * 8);
        }
    }

    // ---- init state ----
    if (tid < 128) {
        int gi = bid * 128 + tid;
        float v = h0l[gi];
        __nv_bfloat16 bh = __float2bfloat16_rn(v);
        __nv_bfloat16 bl = __float2bfloat16_rn(v - __bfloat162float(bh));
        g_hbfh[0][gi] = bh;
        g_hbfl[0][gi] = bl;
        c_sm[tid] = c0l[(tid >> 3) * HIDDEN + bid * 8 + (tid & 7)];
    }
    grid_bar(++tgt);

    // mma lane geometry (identical to verified hmma_gemm)
    int a_r  = lane & 15;
    int a_cb = lane >> 4;
    int b_r  = (lane & 7) + ((lane >> 4) << 3);
    int b_cb = (lane >> 3) & 1;
    int er = lane >> 2, ec = (lane & 3) << 1;

    int pb = tid >> 3, pc = tid & 7;
    int colp = bid * 8 + pc;

    for (int t = 0; t < SEQ; t++) {
        const __nv_bfloat16* hh = g_hbfh[t & 1];
        const __nv_bfloat16* hl = g_hbfl[t & 1];

        // ---- prefetch gatesx (independent of h) ----
        float gx0 = 0.f, gx1 = 0.f, gx2 = 0.f, gx3 = 0.f;
        if (tid < 128) {
            size_t gb = (size_t)(pb * SEQ + t) * GATES + colp;
            gx0 = __ldg(gatesx + gb);
            gx1 = __ldg(gatesx + gb + 1024);
            gx2 = __ldg(gatesx + gb + 2048);
            gx3 = __ldg(gatesx + gb + 3072);
        }

        // ---- per-warp fill of OWN h chunks {2w, 2w+1}: 16 cp16 per lane ----
#pragma unroll
        for (int u = 0; u < 16; u++) {
            int idx = u * 32 + lane;            // 0..511 within warp's work
            int c   = 2 * w + (idx >> 8);       // own chunk
            int rem = idx & 255;
            int arr = rem >> 7;                  // 0=hi, 1=lo
            int rem2 = rem & 127;
            int row = rem2 >> 3;                 // batch 0..15
            int cc  = rem2 & 7;
            uint32_t dst = sbase + (arr ? L_HL : L_HH) + (uint32_t)(c * 2048)
                         + SW128((uint32_t)(row * 128 + cc * 16));
            const __nv_bfloat16* src = (arr ? hl : hh) + row * 1024 + c * 64 + cc * 8;
            cp16(dst, src);
        }
        CP_COMMIT();
        CP_WAIT(0);
        __syncwarp();

        // ---- MMA: warp w handles k-chunks {2w, 2w+1} ----
        float acc[4][4];
#pragma unroll
        for (int i = 0; i < 4; i++)
#pragma unroll
            for (int q = 0; q < 4; q++) acc[i][q] = 0.f;

#pragma unroll
        for (int ci = 0; ci < 2; ci++) {
            int c = 2 * w + ci;
            uint32_t hb = sbase + (uint32_t)(c * 2048);
            uint32_t wb = sbase + (uint32_t)(c * 4096);
#pragma unroll
            for (int kt = 0; kt < 4; kt++) {
                unsigned ah[4], al[4], bh[2][4], bl[2][4];
                {
                    uint32_t off = (uint32_t)(a_r * 128)
                                 + ((((uint32_t)(kt * 2 + a_cb)) ^ ((uint32_t)a_r & 7)) << 4);
                    ldsm_x4(ah, hb + L_HH + off);
                    ldsm_x4(al, hb + L_HL + off);
                }
#pragma unroll
                for (int nt2 = 0; nt2 < 2; nt2++) {
                    int r = b_r + nt2 * 16;
                    uint32_t off = (uint32_t)(r * 128)
                                 + ((((uint32_t)(kt * 2 + b_cb)) ^ ((uint32_t)r & 7)) << 4);
                    ldsm_x4(bh[nt2], wb + L_WH + off);
                    ldsm_x4(bl[nt2], wb + L_WL + off);
                }
#pragma unroll
                for (int nt = 0; nt < 4; nt++) {
                    const unsigned* bhp = &bh[nt >> 1][(nt & 1) * 2];
                    const unsigned* blp = &bl[nt >> 1][(nt & 1) * 2];
                    mma_bf16(acc[nt], ah, bhp);
                    mma_bf16(acc[nt], ah, blp);
                    mma_bf16(acc[nt], al, bhp);
                }
            }
        }

        // ---- stage partials ----
#pragma unroll
        for (int nt = 0; nt < 4; nt++) {
            int col = nt * 8 + ec;
            stage[w * 528 + er * 33 + col]           = acc[nt][0];
            stage[w * 528 + er * 33 + col + 1]       = acc[nt][1];
            stage[w * 528 + (er + 8) * 33 + col]     = acc[nt][2];
            stage[w * 528 + (er + 8) * 33 + col + 1] = acc[nt][3];
        }
        __syncthreads();

        // ---- fused reduce + pointwise (128 threads, fast math) ----
        if (tid < 128) {
            float gi = gx0, gf = gx1, gg = gx2, go = gx3;
#pragma unroll
            for (int q = 0; q < 8; q++) {
                const float* sp = stage + q * 528 + pb * 33;
                gi += sp[pc];
                gf += sp[8 + pc];
                gg += sp[16 + pc];
                go += sp[24 + pc];
            }
            float si = 1.f / (1.f + __expf(-gi));
            float sf = 1.f / (1.f + __expf(-gf));
            float tg = 2.f / (1.f + __expf(-2.f * gg)) - 1.f;
            float so = 1.f / (1.f + __expf(-go));
            float cn = sf * c_sm[tid] + si * tg;
            c_sm[tid] = cn;
            float hn = so * (2.f / (1.f + __expf(-2.f * cn)) - 1.f);

            __nv_bfloat16 bh = __float2bfloat16_rn(hn);
            __nv_bfloat16 bl = __float2bfloat16_rn(hn - __bfloat162float(bh));
            int sidx = pb * HIDDEN + colp;
            g_hbfh[(t + 1) & 1][sidx] = bh;
            g_hbfl[(t + 1) & 1][sidx] = bl;
            size_t hist = (size_t)(pb * SEQ + t) * HIDDEN + colp;
            if (f16hist) {
                ((__half*)g_ah)[hist] = __float2half_rn(hn);
            } else {
                g_ah[hist] = bh;
                g_al[hist] = bl;
            }
            if (t == SEQ - 1) hT[sidx] = hn;
        }
        grid_bar(++tgt);
    }
    if (tid < 128)
        cT[pb * HIDDEN + colp] = c_sm[tid];
}

// ------------------------- launch -------------------------
extern "C" void kernel_launch(void* const* d_in, const int* in_sizes, int n_in,
                              void* d_out, int out_size) {
    const int*   x     = (const int*)  d_in[0];
    const float* h0    = (const float*)d_in[1];
    const float* c0    = (const float*)d_in[2];
    const float* emb   = (const float*)d_in[3];
    const float* W_ih0 = (const float*)d_in[4];
    const float* W_hh0 = (const float*)d_in[5];
    const float* b_ih0 = (const float*)d_in[6];
    const float* b_hh0 = (const float*)d_in[7];
    const float* W_ih1 = (const float*)d_in[8];
    const float* W_hh1 = (const float*)d_in[9];
    const float* b_ih1 = (const float*)d_in[10];
    const float* b_hh1 = (const float*)d_in[11];
    const float* fc_W  = (const float*)d_in[12];
    const float* fc_b  = (const float*)d_in[13];

    float* out    = (float*)d_out;
    float* logits = out;
    float* hT     = out + (size_t)MROWS * VOCAB;
    float* cT     = hT + 2 * BATCH * HIDDEN;

    float* p_gatesx;
    __nv_bfloat16 *p_ah, *p_al, *p_wh, *p_wl, *p_whh_h, *p_whh_l;
    cudaGetSymbolAddress((void**)&p_gatesx, g_gatesx);
    cudaGetSymbolAddress((void**)&p_ah, g_ah);
    cudaGetSymbolAddress((void**)&p_al, g_al);
    cudaGetSymbolAddress((void**)&p_wh, g_wh);
    cudaGetSymbolAddress((void**)&p_wl, g_wl);
    cudaGetSymbolAddress((void**)&p_whh_h, g_whh_h);
    cudaGetSymbolAddress((void**)&p_whh_l, g_whh_l);

    const int GSM   = 1024 + 2 * 65536;
    const int GSM16 = 1024 + 2 * 32768;
    cudaFuncSetAttribute(hmma_gemm, cudaFuncAttributeMaxDynamicSharedMemorySize, GSM);
    cudaFuncSetAttribute(hmma_gemm_f16, cudaFuncAttributeMaxDynamicSharedMemorySize, GSM16);
    cudaFuncSetAttribute(lstm_layer, cudaFuncAttributeMaxDynamicSharedMemorySize, L_DYN);

    const int SH = BATCH * HIDDEN;

    // layer 0
    embed_cvt<<<MROWS * 64 / 256, 256>>>(x, emb, p_ah, p_al);
    cvt_hilo<<<GATES * EMBED / 8 / 256, 256>>>(W_ih0, p_wh, p_wl, GATES * EMBED / 8);
    cvt_hilo<<<GATES * HIDDEN / 8 / 256, 256>>>(W_hh0, p_whh_h, p_whh_l, GATES * HIDDEN / 8);
    hmma_gemm<<<dim3(MROWS / 128, GATES / 128), 256, GSM>>>(
        p_ah, p_al, p_wh, p_wl, b_ih0, b_hh0, p_gatesx, GATES, EMBED);
    lstm_layer<<<NBLK, 256, L_DYN>>>(p_whh_h, p_whh_l, p_gatesx, h0, c0, hT, cT, 0);

    // layer 1 (lstm0 wrote bf16 hi/lo history into g_ah/g_al)
    cvt_hilo<<<GATES * HIDDEN / 8 / 256, 256>>>(W_ih1, p_wh, p_wl, GATES * HIDDEN / 8);
    cvt_hilo<<<GATES * HIDDEN / 8 / 256, 256>>>(W_hh1, p_whh_h, p_whh_l, GATES * HIDDEN / 8);
    hmma_gemm<<<dim3(MROWS / 128, GATES / 128), 256, GSM>>>(
        p_ah, p_al, p_wh, p_wl, b_ih1, b_hh1, p_gatesx, GATES, HIDDEN);
    lstm_layer<<<NBLK, 256, L_DYN>>>(p_whh_h, p_whh_l, p_gatesx, h0 + SH, c0 + SH,
                                     hT + SH, cT + SH, 1);

    // FC head: single-term fp16 (lstm1 wrote fp16 history into g_ah)
    cvt_f16<<<VOCAB * HIDDEN / 8 / 256, 256>>>(fc_W, (__half*)p_wh, VOCAB * HIDDEN / 8);
    hmma_gemm_f16<<<dim3(MROWS / 128, VOCAB / 128), 256, GSM16>>>(
        (const __half*)p_ah, (const __half*)p_wh, fc_b, logits, VOCAB, HIDDEN);
}

// round 14
// speedup vs baseline: 1.0922x; 1.0922x over previous
#include <cuda_runtime.h>
#include <cuda_bf16.h>
#include <cuda_fp16.h>
#include <cstdint>

#define BATCH   16
#define SEQ     256
#define EMBED   512
#define HIDDEN  1024
#define GATES   (4 * HIDDEN)
#define VOCAB   32000
#define MROWS   (BATCH * SEQ)
#define NBLK    128
typedef unsigned long long ull;

// ------------------------- scratch (device globals) -------------------------
__device__ float g_gatesx[MROWS * GATES];
__device__ __nv_bfloat16 g_ah[MROWS * HIDDEN];        // A-history hi (bf16) or fp16 single
__device__ __nv_bfloat16 g_al[MROWS * HIDDEN];        // A-history lo (bf16)
__device__ __nv_bfloat16 g_wh[(size_t)VOCAB * HIDDEN];
__device__ __nv_bfloat16 g_wl[(size_t)VOCAB * HIDDEN];
__device__ __half g_whh16[GATES * HIDDEN];            // W_hh fp16 (recurrence)
__device__ __half g_hf16[2][BATCH * HIDDEN];          // recurrent h state, fp16
__device__ unsigned g_cnt;
__device__ volatile unsigned g_gen;

// ------------------------- HMMA / smem helpers (plain sm_103-safe) ----------
__device__ __forceinline__ uint32_t smem_u32(const void* p) {
    uint32_t a;
    asm("{ .reg .u64 t; cvta.to.shared.u64 t, %1; cvt.u32.u64 %0, t; }" : "=r"(a) : "l"(p));
    return a;
}
__device__ __forceinline__ void mma_bf16(float* d, const unsigned* a, const unsigned* b) {
    asm volatile("mma.sync.aligned.m16n8k16.row.col.f32.bf16.bf16.f32 "
        "{%0,%1,%2,%3}, {%4,%5,%6,%7}, {%8,%9}, {%0,%1,%2,%3};"
        : "+f"(d[0]), "+f"(d[1]), "+f"(d[2]), "+f"(d[3])
        : "r"(a[0]), "r"(a[1]), "r"(a[2]), "r"(a[3]), "r"(b[0]), "r"(b[1]));
}
__device__ __forceinline__ void mma_f16h(float* d, const unsigned* a, const unsigned* b) {
    asm volatile("mma.sync.aligned.m16n8k16.row.col.f32.f16.f16.f32 "
        "{%0,%1,%2,%3}, {%4,%5,%6,%7}, {%8,%9}, {%0,%1,%2,%3};"
        : "+f"(d[0]), "+f"(d[1]), "+f"(d[2]), "+f"(d[3])
        : "r"(a[0]), "r"(a[1]), "r"(a[2]), "r"(a[3]), "r"(b[0]), "r"(b[1]));
}
__device__ __forceinline__ void ldsm_x4(unsigned* r, uint32_t addr) {
    asm volatile("ldmatrix.sync.aligned.m8n8.x4.shared.b16 {%0,%1,%2,%3}, [%4];"
        : "=r"(r[0]), "=r"(r[1]), "=r"(r[2]), "=r"(r[3]) : "r"(addr));
}
__device__ __forceinline__ void cp16(uint32_t dst, const void* src) {
    asm volatile("cp.async.cg.shared.global [%0], [%1], 16;" :: "r"(dst), "l"(src));
}
#define CP_COMMIT()  asm volatile("cp.async.commit_group;" ::: "memory")
#define CP_WAIT(n)   asm volatile("cp.async.wait_group %0;" :: "n"(n) : "memory")
#define SW128(o) ((o) ^ (((o) >> 3) & 0x70))

// ------------------------- flat grid barrier (proven fastest) ---------------
__device__ __forceinline__ void grid_bar(unsigned target) {
    __threadfence();
    __syncthreads();
    if (threadIdx.x == 0) {
        unsigned arr = atomicAdd(&g_cnt, 1u);
        if (arr == NBLK - 1) { g_cnt = 0; __threadfence(); g_gen = target; }
        else { while ((int)(g_gen - target) < 0) {} __threadfence(); }
    }
    __syncthreads();
}

// ------------------------- fp32 -> bf16 hi/lo split -------------------------
__device__ __forceinline__ void split8(float4 v0, float4 v1, uint4& hi, uint4& lo) {
    float f[8] = {v0.x, v0.y, v0.z, v0.w, v1.x, v1.y, v1.z, v1.w};
    unsigned short h[8], l[8];
#pragma unroll
    for (int i = 0; i < 8; i++) {
        __nv_bfloat16 bh = __float2bfloat16_rn(f[i]);
        __nv_bfloat16 bl = __float2bfloat16_rn(f[i] - __bfloat162float(bh));
        h[i] = __bfloat16_as_ushort(bh); l[i] = __bfloat16_as_ushort(bl);
    }
    hi = make_uint4(h[0]|((uint32_t)h[1]<<16), h[2]|((uint32_t)h[3]<<16),
                    h[4]|((uint32_t)h[5]<<16), h[6]|((uint32_t)h[7]<<16));
    lo = make_uint4(l[0]|((uint32_t)l[1]<<16), l[2]|((uint32_t)l[3]<<16),
                    l[4]|((uint32_t)l[5]<<16), l[6]|((uint32_t)l[7]<<16));
}

__global__ void cvt_hilo(const float* __restrict__ src,
                         __nv_bfloat16* __restrict__ hi,
                         __nv_bfloat16* __restrict__ lo, int n8) {
    int i = blockIdx.x * 256 + threadIdx.x;
    if (i >= n8) return;
    const float4* s = (const float4*)src + 2 * (size_t)i;
    uint4 h, l; split8(s[0], s[1], h, l);
    ((uint4*)hi)[i] = h; ((uint4*)lo)[i] = l;
}

// fp32 -> fp16 single
__global__ void cvt_f16(const float* __restrict__ src, __half* __restrict__ dst, int n8) {
    int i = blockIdx.x * 256 + threadIdx.x;
    if (i >= n8) return;
    const float4* s = (const float4*)src + 2 * (size_t)i;
    float4 v0 = s[0], v1 = s[1];
    __half2 p0 = __floats2half2_rn(v0.x, v0.y);
    __half2 p1 = __floats2half2_rn(v0.z, v0.w);
    __half2 p2 = __floats2half2_rn(v1.x, v1.y);
    __half2 p3 = __floats2half2_rn(v1.z, v1.w);
    uint4 o;
    o.x = *(unsigned*)&p0; o.y = *(unsigned*)&p1;
    o.z = *(unsigned*)&p2; o.w = *(unsigned*)&p3;
    ((uint4*)dst)[i] = o;
}

__global__ void embed_cvt(const int* __restrict__ x, const float* __restrict__ emb,
                          __nv_bfloat16* __restrict__ hi, __nv_bfloat16* __restrict__ lo) {
    int idx = blockIdx.x * 256 + threadIdx.x;
    int row = idx >> 6;
    int e8  = idx & 63;
    const float4* s = (const float4*)(emb + ((size_t)x[row] << 9)) + 2 * e8;
    uint4 h, l; split8(s[0], s[1], h, l);
    ((uint4*)hi)[idx] = h; ((uint4*)lo)[idx] = l;
}

// ------------------------- HMMA GEMM 3-term bf16 (verified R8) --------------
__device__ __forceinline__ void gemm_load_chunk(
    const __nv_bfloat16* Ah, const __nv_bfloat16* Al,
    const __nv_bfloat16* Bh, const __nv_bfloat16* Bl,
    int m0, int n0, int K, int c, uint32_t sbase, int tid) {
    uint32_t sb = sbase + (c & 1) * 65536;
    int kb = c << 6;
#pragma unroll
    for (int it = 0; it < 4; it++) {
        int idx = it * 256 + tid;
        int row = idx >> 3, cc = idx & 7;
        uint32_t dst = SW128((uint32_t)(row * 128 + cc * 16));
        size_t ga = (size_t)(m0 + row) * K + kb + cc * 8;
        size_t gb = (size_t)(n0 + row) * K + kb + cc * 8;
        cp16(sb + dst,         Ah + ga);
        cp16(sb + 16384 + dst, Al + ga);
        cp16(sb + 32768 + dst, Bh + gb);
        cp16(sb + 49152 + dst, Bl + gb);
    }
    CP_COMMIT();
}

__global__ __launch_bounds__(256)
void hmma_gemm(const __nv_bfloat16* __restrict__ Ah, const __nv_bfloat16* __restrict__ Al,
               const __nv_bfloat16* __restrict__ Bh, const __nv_bfloat16* __restrict__ Bl,
               const float* __restrict__ b1, const float* __restrict__ b2,
               float* __restrict__ C, int N, int K) {
    extern __shared__ char dsm[];
    uint32_t raw = smem_u32(dsm);
    uint32_t sbase = (raw + 1023) & ~1023u;

    int tid = threadIdx.x, wid = tid >> 5, lane = tid & 31;
    int m0 = blockIdx.x << 7, n0 = blockIdx.y << 7;
    int NC = K >> 6;

    gemm_load_chunk(Ah, Al, Bh, Bl, m0, n0, K, 0, sbase, tid);
    gemm_load_chunk(Ah, Al, Bh, Bl, m0, n0, K, 1, sbase, tid);

    int wm = wid >> 2, wn = wid & 3;
    int mb = wm * 64, nb = wn * 32;

    float acc[4][4][4];
#pragma unroll
    for (int i = 0; i < 4; i++)
#pragma unroll
        for (int j = 0; j < 4; j++)
#pragma unroll
            for (int q = 0; q < 4; q++) acc[i][j][q] = 0.f;

    int a_r = mb + (lane & 15);
    int a_cb = lane >> 4;
    int b_r = nb + (lane & 7) + ((lane >> 4) << 3);
    int b_cb = (lane >> 3) & 1;

    for (int c = 0; c < NC; c++) {
        if (c + 1 < NC) { CP_WAIT(1); } else { CP_WAIT(0); }
        __syncthreads();
        uint32_t sb = sbase + (c & 1) * 65536;
#pragma unroll
        for (int kt = 0; kt < 4; kt++) {
            unsigned ah[4][4], al[4][4], bh[2][4], bl[2][4];
#pragma unroll
            for (int mt = 0; mt < 4; mt++) {
                int r = a_r + mt * 16;
                uint32_t off = (uint32_t)(r * 128)
                             + ((((uint32_t)(kt * 2 + a_cb)) ^ ((uint32_t)r & 7)) << 4);
                ldsm_x4(ah[mt], sb + off);
                ldsm_x4(al[mt], sb + 16384 + off);
            }
#pragma unroll
            for (int nt2 = 0; nt2 < 2; nt2++) {
                int r = b_r + nt2 * 16;
                uint32_t off = (uint32_t)(r * 128)
                             + ((((uint32_t)(kt * 2 + b_cb)) ^ ((uint32_t)r & 7)) << 4);
                ldsm_x4(bh[nt2], sb + 32768 + off);
                ldsm_x4(bl[nt2], sb + 49152 + off);
            }
#pragma unroll
            for (int mt = 0; mt < 4; mt++)
#pragma unroll
                for (int nt = 0; nt < 4; nt++) {
                    const unsigned* bhp = &bh[nt >> 1][(nt & 1) * 2];
                    const unsigned* blp = &bl[nt >> 1][(nt & 1) * 2];
                    mma_bf16(acc[mt][nt], ah[mt], bhp);
                    mma_bf16(acc[mt][nt], ah[mt], blp);
                    mma_bf16(acc[mt][nt], al[mt], bhp);
                }
        }
        __syncthreads();
        if (c + 2 < NC)
            gemm_load_chunk(Ah, Al, Bh, Bl, m0, n0, K, c + 2, sbase, tid);
    }

    int er = lane >> 2;
    int ec = (lane & 3) << 1;
#pragma unroll
    for (int nt = 0; nt < 4; nt++) {
        int col = n0 + nb + nt * 8 + ec;
        float2 bv = *(const float2*)(b1 + col);
        if (b2) {
            float2 t2 = *(const float2*)(b2 + col);
            bv.x += t2.x; bv.y += t2.y;
        }
#pragma unroll
        for (int mt = 0; mt < 4; mt++) {
            int r0 = m0 + mb + mt * 16 + er;
            *(float2*)(C + (size_t)r0 * N + col) =
                make_float2(acc[mt][nt][0] + bv.x, acc[mt][nt][1] + bv.y);
            *(float2*)(C + (size_t)(r0 + 8) * N + col) =
                make_float2(acc[mt][nt][2] + bv.x, acc[mt][nt][3] + bv.y);
        }
    }
}

// ------------------------- HMMA GEMM single-term fp16 (FC head) -------------
__device__ __forceinline__ void gemm_load_chunk_f16(
    const __half* A, const __half* B,
    int m0, int n0, int K, int c, uint32_t sbase, int tid) {
    uint32_t sb = sbase + (c & 1) * 32768;
    int kb = c << 6;
#pragma unroll
    for (int it = 0; it < 4; it++) {
        int idx = it * 256 + tid;
        int row = idx >> 3, cc = idx & 7;
        uint32_t dst = SW128((uint32_t)(row * 128 + cc * 16));
        cp16(sb + dst,         A + (size_t)(m0 + row) * K + kb + cc * 8);
        cp16(sb + 16384 + dst, B + (size_t)(n0 + row) * K + kb + cc * 8);
    }
    CP_COMMIT();
}

__global__ __launch_bounds__(256)
void hmma_gemm_f16(const __half* __restrict__ A, const __half* __restrict__ B,
                   const float* __restrict__ b1,
                   float* __restrict__ C, int N, int K) {
    extern __shared__ char dsm[];
    uint32_t raw = smem_u32(dsm);
    uint32_t sbase = (raw + 1023) & ~1023u;

    int tid = threadIdx.x, wid = tid >> 5, lane = tid & 31;
    int m0 = blockIdx.x << 7, n0 = blockIdx.y << 7;
    int NC = K >> 6;

    gemm_load_chunk_f16(A, B, m0, n0, K, 0, sbase, tid);
    gemm_load_chunk_f16(A, B, m0, n0, K, 1, sbase, tid);

    int wm = wid >> 2, wn = wid & 3;
    int mb = wm * 64, nb = wn * 32;

    float acc[4][4][4];
#pragma unroll
    for (int i = 0; i < 4; i++)
#pragma unroll
        for (int j = 0; j < 4; j++)
#pragma unroll
            for (int q = 0; q < 4; q++) acc[i][j][q] = 0.f;

    int a_r = mb + (lane & 15);
    int a_cb = lane >> 4;
    int b_r = nb + (lane & 7) + ((lane >> 4) << 3);
    int b_cb = (lane >> 3) & 1;

    for (int c = 0; c < NC; c++) {
        if (c + 1 < NC) { CP_WAIT(1); } else { CP_WAIT(0); }
        __syncthreads();
        uint32_t sb = sbase + (c & 1) * 32768;
#pragma unroll
        for (int kt = 0; kt < 4; kt++) {
            unsigned ah[4][4], bh[2][4];
#pragma unroll
            for (int mt = 0; mt < 4; mt++) {
                int r = a_r + mt * 16;
                uint32_t off = (uint32_t)(r * 128)
                             + ((((uint32_t)(kt * 2 + a_cb)) ^ ((uint32_t)r & 7)) << 4);
                ldsm_x4(ah[mt], sb + off);
            }
#pragma unroll
            for (int nt2 = 0; nt2 < 2; nt2++) {
                int r = b_r + nt2 * 16;
                uint32_t off = (uint32_t)(r * 128)
                             + ((((uint32_t)(kt * 2 + b_cb)) ^ ((uint32_t)r & 7)) << 4);
                ldsm_x4(bh[nt2], sb + 16384 + off);
            }
#pragma unroll
            for (int mt = 0; mt < 4; mt++)
#pragma unroll
                for (int nt = 0; nt < 4; nt++)
                    mma_f16h(acc[mt][nt], ah[mt], &bh[nt >> 1][(nt & 1) * 2]);
        }
        __syncthreads();
        if (c + 2 < NC)
            gemm_load_chunk_f16(A, B, m0, n0, K, c + 2, sbase, tid);
    }

    int er = lane >> 2;
    int ec = (lane & 3) << 1;
#pragma unroll
    for (int nt = 0; nt < 4; nt++) {
        int col = n0 + nb + nt * 8 + ec;
        float2 bv = *(const float2*)(b1 + col);
#pragma unroll
        for (int mt = 0; mt < 4; mt++) {
            int r0 = m0 + mb + mt * 16 + er;
            *(float2*)(C + (size_t)r0 * N + col) =
                make_float2(acc[mt][nt][0] + bv.x, acc[mt][nt][1] + bv.y);
            *(float2*)(C + (size_t)(r0 + 8) * N + col) =
                make_float2(acc[mt][nt][2] + bv.x, acc[mt][nt][3] + bv.y);
        }
    }
}

// ------------------------- persistent LSTM layer (fp16 recurrence) ----------
// Recurrent GEMM single-term fp16: W smem 64KB, h smem 32KB, 32 MMAs/warp/step.
// Projections (gatesx) remain 3-term bf16 — precision lives there.
#define L_W   0                             // fp16 W_hh slice: 16 chunks x 4KB
#define L_H   65536                         // fp16 h tiles:    16 chunks x 2KB
#define L_ST  98304                         // float stage[8][16][33]
#define L_DYN (1024 + 98304 + 16896)

__global__ __launch_bounds__(256)
void lstm_layer(const __half* __restrict__ Whh16,
                const float* __restrict__ gatesx,
                const float* __restrict__ h0l, const float* __restrict__ c0l,
                float* __restrict__ hT, float* __restrict__ cT, int f16hist) {
    extern __shared__ char dsm[];
    __shared__ float c_sm[128];
    __shared__ unsigned base_sh;

    uint32_t raw = smem_u32(dsm);
    uint32_t sbase = (raw + 1023) & ~1023u;
    char* smp = dsm + (sbase - raw);
    float* stage = (float*)(smp + L_ST);

    int tid = threadIdx.x, bid = blockIdx.x;
    int w = tid >> 5, lane = tid & 31;

    if (tid == 0) base_sh = g_gen;
    __syncthreads();
    unsigned tgt = base_sh;

    // ---- W_hh fp16 slice load (once per layer): 512 (row,chunk) pairs ----
    for (int p = tid * 2; p < tid * 2 + 2; p++) {
        int l = p >> 4, c = p & 15;
        size_t grow = (size_t)((l >> 3) * HIDDEN + bid * 8 + (l & 7)) * HIDDEN + c * 64;
        uint32_t cb = (uint32_t)(c * 4096);
#pragma unroll
        for (int cc = 0; cc < 8; cc++) {
            uint32_t sw = cb + SW128((uint32_t)(l * 128 + cc * 16));
            *(uint4*)(smp + L_W + sw) = *(const uint4*)(Whh16 + grow + cc * 8);
        }
    }

    // ---- init state ----
    if (tid < 128) {
        int gi = bid * 128 + tid;
        g_hf16[0][gi] = __float2half_rn(h0l[gi]);
        c_sm[tid] = c0l[(tid >> 3) * HIDDEN + bid * 8 + (tid & 7)];
    }
    grid_bar(++tgt);

    // mma lane geometry (identical to verified hmma_gemm_f16)
    int a_r  = lane & 15;
    int a_cb = lane >> 4;
    int b_r  = (lane & 7) + ((lane >> 4) << 3);
    int b_cb = (lane >> 3) & 1;
    int er = lane >> 2, ec = (lane & 3) << 1;

    int pb = tid >> 3, pc = tid & 7;
    int colp = bid * 8 + pc;

    for (int t = 0; t < SEQ; t++) {
        const __half* hf = g_hf16[t & 1];

        // ---- prefetch gatesx (independent of h) ----
        float gx0 = 0.f, gx1 = 0.f, gx2 = 0.f, gx3 = 0.f;
        if (tid < 128) {
            size_t gb = (size_t)(pb * SEQ + t) * GATES + colp;
            gx0 = __ldg(gatesx + gb);
            gx1 = __ldg(gatesx + gb + 1024);
            gx2 = __ldg(gatesx + gb + 2048);
            gx3 = __ldg(gatesx + gb + 3072);
        }

        // ---- fill h tiles (fp16): 8 cp16 per thread, block-wide ----
#pragma unroll
        for (int u = 0; u < 8; u++) {
            int idx = u * 256 + tid;            // 0..2047
            int c   = idx >> 7;
            int rem = idx & 127;
            int row = rem >> 3;
            int cc  = rem & 7;
            uint32_t dst = sbase + L_H + (uint32_t)(c * 2048)
                         + SW128((uint32_t)(row * 128 + cc * 16));
            cp16(dst, hf + row * 1024 + c * 64 + cc * 8);
        }
        CP_COMMIT();
        CP_WAIT(0);
        __syncthreads();

        // ---- MMA: warp w handles k-chunks {2w, 2w+1}, single fp16 term ----
        float acc[4][4];
#pragma unroll
        for (int i = 0; i < 4; i++)
#pragma unroll
            for (int q = 0; q < 4; q++) acc[i][q] = 0.f;

#pragma unroll
        for (int ci = 0; ci < 2; ci++) {
            int c = 2 * w + ci;
            uint32_t hb = sbase + L_H + (uint32_t)(c * 2048);
            uint32_t wb = sbase + L_W + (uint32_t)(c * 4096);
#pragma unroll
            for (int kt = 0; kt < 4; kt++) {
                unsigned ah[4], bh[2][4];
                {
                    uint32_t off = (uint32_t)(a_r * 128)
                                 + ((((uint32_t)(kt * 2 + a_cb)) ^ ((uint32_t)a_r & 7)) << 4);
                    ldsm_x4(ah, hb + off);
                }
#pragma unroll
                for (int nt2 = 0; nt2 < 2; nt2++) {
                    int r = b_r + nt2 * 16;
                    uint32_t off = (uint32_t)(r * 128)
                                 + ((((uint32_t)(kt * 2 + b_cb)) ^ ((uint32_t)r & 7)) << 4);
                    ldsm_x4(bh[nt2], wb + off);
                }
#pragma unroll
                for (int nt = 0; nt < 4; nt++)
                    mma_f16h(acc[nt], ah, &bh[nt >> 1][(nt & 1) * 2]);
            }
        }

        // ---- stage partials ----
#pragma unroll
        for (int nt = 0; nt < 4; nt++) {
            int col = nt * 8 + ec;
            stage[w * 528 + er * 33 + col]           = acc[nt][0];
            stage[w * 528 + er * 33 + col + 1]       = acc[nt][1];
            stage[w * 528 + (er + 8) * 33 + col]     = acc[nt][2];
            stage[w * 528 + (er + 8) * 33 + col + 1] = acc[nt][3];
        }
        __syncthreads();

        // ---- fused reduce + pointwise (128 threads, fast math) ----
        if (tid < 128) {
            float gi = gx0, gf = gx1, gg = gx2, go = gx3;
#pragma unroll
            for (int q = 0; q < 8; q++) {
                const float* sp = stage + q * 528 + pb * 33;
                gi += sp[pc];
                gf += sp[8 + pc];
                gg += sp[16 + pc];
                go += sp[24 + pc];
            }
            float si = 1.f / (1.f + __expf(-gi));
            float sf = 1.f / (1.f + __expf(-gf));
            float tg = 2.f / (1.f + __expf(-2.f * gg)) - 1.f;
            float so = 1.f / (1.f + __expf(-go));
            float cn = sf * c_sm[tid] + si * tg;
            c_sm[tid] = cn;
            float hn = so * (2.f / (1.f + __expf(-2.f * cn)) - 1.f);

            int sidx = pb * HIDDEN + colp;
            g_hf16[(t + 1) & 1][sidx] = __float2half_rn(hn);
            size_t hist = (size_t)(pb * SEQ + t) * HIDDEN + colp;
            if (f16hist) {
                ((__half*)g_ah)[hist] = __float2half_rn(hn);
            } else {
                __nv_bfloat16 bh = __float2bfloat16_rn(hn);
                g_ah[hist] = bh;
                g_al[hist] = __float2bfloat16_rn(hn - __bfloat162float(bh));
            }
            if (t == SEQ - 1) hT[sidx] = hn;
        }
        grid_bar(++tgt);
    }
    if (tid < 128)
        cT[pb * HIDDEN + colp] = c_sm[tid];
}

// ------------------------- launch -------------------------
extern "C" void kernel_launch(void* const* d_in, const int* in_sizes, int n_in,
                              void* d_out, int out_size) {
    const int*   x     = (const int*)  d_in[0];
    const float* h0    = (const float*)d_in[1];
    const float* c0    = (const float*)d_in[2];
    const float* emb   = (const float*)d_in[3];
    const float* W_ih0 = (const float*)d_in[4];
    const float* W_hh0 = (const float*)d_in[5];
    const float* b_ih0 = (const float*)d_in[6];
    const float* b_hh0 = (const float*)d_in[7];
    const float* W_ih1 = (const float*)d_in[8];
    const float* W_hh1 = (const float*)d_in[9];
    const float* b_ih1 = (const float*)d_in[10];
    const float* b_hh1 = (const float*)d_in[11];
    const float* fc_W  = (const float*)d_in[12];
    const float* fc_b  = (const float*)d_in[13];

    float* out    = (float*)d_out;
    float* logits = out;
    float* hT     = out + (size_t)MROWS * VOCAB;
    float* cT     = hT + 2 * BATCH * HIDDEN;

    float* p_gatesx;
    __nv_bfloat16 *p_ah, *p_al, *p_wh, *p_wl;
    __half* p_whh16;
    cudaGetSymbolAddress((void**)&p_gatesx, g_gatesx);
    cudaGetSymbolAddress((void**)&p_ah, g_ah);
    cudaGetSymbolAddress((void**)&p_al, g_al);
    cudaGetSymbolAddress((void**)&p_wh, g_wh);
    cudaGetSymbolAddress((void**)&p_wl, g_wl);
    cudaGetSymbolAddress((void**)&p_whh16, g_whh16);

    const int GSM   = 1024 + 2 * 65536;
    const int GSM16 = 1024 + 2 * 32768;
    cudaFuncSetAttribute(hmma_gemm, cudaFuncAttributeMaxDynamicSharedMemorySize, GSM);
    cudaFuncSetAttribute(hmma_gemm_f16, cudaFuncAttributeMaxDynamicSharedMemorySize, GSM16);
    cudaFuncSetAttribute(lstm_layer, cudaFuncAttributeMaxDynamicSharedMemorySize, L_DYN);

    const int SH = BATCH * HIDDEN;

    // layer 0
    embed_cvt<<<MROWS * 64 / 256, 256>>>(x, emb, p_ah, p_al);
    cvt_hilo<<<GATES * EMBED / 8 / 256, 256>>>(W_ih0, p_wh, p_wl, GATES * EMBED / 8);
    cvt_f16<<<GATES * HIDDEN / 8 / 256, 256>>>(W_hh0, p_whh16, GATES * HIDDEN / 8);
    hmma_gemm<<<dim3(MROWS / 128, GATES / 128), 256, GSM>>>(
        p_ah, p_al, p_wh, p_wl, b_ih0, b_hh0, p_gatesx, GATES, EMBED);
    lstm_layer<<<NBLK, 256, L_DYN>>>(p_whh16, p_gatesx, h0, c0, hT, cT, 0);

    // layer 1 (lstm0 wrote bf16 hi/lo history into g_ah/g_al)
    cvt_hilo<<<GATES * HIDDEN / 8 / 256, 256>>>(W_ih1, p_wh, p_wl, GATES * HIDDEN / 8);
    cvt_f16<<<GATES * HIDDEN / 8 / 256, 256>>>(W_hh1, p_whh16, GATES * HIDDEN / 8);
    hmma_gemm<<<dim3(MROWS / 128, GATES / 128), 256, GSM>>>(
        p_ah, p_al, p_wh, p_wl, b_ih1, b_hh1, p_gatesx, GATES, HIDDEN);
    lstm_layer<<<NBLK, 256, L_DYN>>>(p_whh16, p_gatesx, h0 + SH, c0 + SH,
                                     hT + SH, cT + SH, 1);

    // FC head: single-term fp16 (lstm1 wrote fp16 history into g_ah)
    cvt_f16<<<VOCAB * HIDDEN / 8 / 256, 256>>>(fc_W, (__half*)p_wh, VOCAB * HIDDEN / 8);
    hmma_gemm_f16<<<dim3(MROWS / 128, VOCAB / 128), 256, GSM16>>>(
        (const __half*)p_ah, (const __half*)p_wh, fc_b, logits, VOCAB, HIDDEN);
}

// round 15
// speedup vs baseline: 1.1912x; 1.0906x over previous
#include <cuda_runtime.h>
#include <cuda_fp16.h>
#include <cstdint>

#define BATCH   16
#define SEQ     256
#define EMBED   512
#define HIDDEN  1024
#define GATES   (4 * HIDDEN)
#define VOCAB   32000
#define MROWS   (BATCH * SEQ)
#define NBLK    128
typedef unsigned long long ull;

// ------------------------- scratch (device globals) -------------------------
__device__ float g_gatesx[MROWS * GATES];             // 64 MB preacts
__device__ __half g_hist16[MROWS * HIDDEN];           //  8 MB A-history (fp16)
__device__ __half g_w16[(size_t)VOCAB * HIDDEN];      // 64 MB weight buffer (fp16)
__device__ __half g_whh16[GATES * HIDDEN];            //  8 MB W_hh (fp16)
__device__ __half g_hf16[2][BATCH * HIDDEN];          // recurrent h state, fp16
__device__ unsigned g_cnt;
__device__ volatile unsigned g_gen;

// ------------------------- HMMA / smem helpers (plain sm_103-safe) ----------
__device__ __forceinline__ uint32_t smem_u32(const void* p) {
    uint32_t a;
    asm("{ .reg .u64 t; cvta.to.shared.u64 t, %1; cvt.u32.u64 %0, t; }" : "=r"(a) : "l"(p));
    return a;
}
__device__ __forceinline__ void mma_f16h(float* d, const unsigned* a, const unsigned* b) {
    asm volatile("mma.sync.aligned.m16n8k16.row.col.f32.f16.f16.f32 "
        "{%0,%1,%2,%3}, {%4,%5,%6,%7}, {%8,%9}, {%0,%1,%2,%3};"
        : "+f"(d[0]), "+f"(d[1]), "+f"(d[2]), "+f"(d[3])
        : "r"(a[0]), "r"(a[1]), "r"(a[2]), "r"(a[3]), "r"(b[0]), "r"(b[1]));
}
__device__ __forceinline__ void ldsm_x4(unsigned* r, uint32_t addr) {
    asm volatile("ldmatrix.sync.aligned.m8n8.x4.shared.b16 {%0,%1,%2,%3}, [%4];"
        : "=r"(r[0]), "=r"(r[1]), "=r"(r[2]), "=r"(r[3]) : "r"(addr));
}
__device__ __forceinline__ void cp16(uint32_t dst, const void* src) {
    asm volatile("cp.async.cg.shared.global [%0], [%1], 16;" :: "r"(dst), "l"(src));
}
#define CP_COMMIT()  asm volatile("cp.async.commit_group;" ::: "memory")
#define CP_WAIT(n)   asm volatile("cp.async.wait_group %0;" :: "n"(n) : "memory")
#define SW128(o) ((o) ^ (((o) >> 3) & 0x70))

// ------------------------- flat grid barrier (proven fastest) ---------------
__device__ __forceinline__ void grid_bar(unsigned target) {
    __threadfence();
    __syncthreads();
    if (threadIdx.x == 0) {
        unsigned arr = atomicAdd(&g_cnt, 1u);
        if (arr == NBLK - 1) { g_cnt = 0; __threadfence(); g_gen = target; }
        else { while ((int)(g_gen - target) < 0) {} __threadfence(); }
    }
    __syncthreads();
}

// ------------------------- fp32 -> fp16 convert ------------------------------
__global__ void cvt_f16(const float* __restrict__ src, __half* __restrict__ dst, int n8) {
    int i = blockIdx.x * 256 + threadIdx.x;
    if (i >= n8) return;
    const float4* s = (const float4*)src + 2 * (size_t)i;
    float4 v0 = s[0], v1 = s[1];
    __half2 p0 = __floats2half2_rn(v0.x, v0.y);
    __half2 p1 = __floats2half2_rn(v0.z, v0.w);
    __half2 p2 = __floats2half2_rn(v1.x, v1.y);
    __half2 p3 = __floats2half2_rn(v1.z, v1.w);
    uint4 o;
    o.x = *(unsigned*)&p0; o.y = *(unsigned*)&p1;
    o.z = *(unsigned*)&p2; o.w = *(unsigned*)&p3;
    ((uint4*)dst)[i] = o;
}

// embedding gather -> fp16
__global__ void embed_cvt16(const int* __restrict__ x, const float* __restrict__ emb,
                            __half* __restrict__ dst) {
    int idx = blockIdx.x * 256 + threadIdx.x;   // 8-elem units
    int row = idx >> 6;                          // EMBED/8 = 64 per row
    int e8  = idx & 63;
    const float4* s = (const float4*)(emb + ((size_t)x[row] << 9)) + 2 * e8;
    float4 v0 = s[0], v1 = s[1];
    __half2 p0 = __floats2half2_rn(v0.x, v0.y);
    __half2 p1 = __floats2half2_rn(v0.z, v0.w);
    __half2 p2 = __floats2half2_rn(v1.x, v1.y);
    __half2 p3 = __floats2half2_rn(v1.z, v1.w);
    uint4 o;
    o.x = *(unsigned*)&p0; o.y = *(unsigned*)&p1;
    o.z = *(unsigned*)&p2; o.w = *(unsigned*)&p3;
    ((uint4*)dst)[idx] = o;
}

// ------------------------- HMMA GEMM fp16 (unified) -------------------------
// C[m,n] = A[M,K] @ B[N,K]^T + b1 (+ b2). 128x128 CTA tile, 8 warps (64x32),
// cp.async double buffer, SW128 swizzle. M%128==0, N%128==0, K%64==0, K>=128.
__device__ __forceinline__ void gemm_load_chunk_f16(
    const __half* A, const __half* B,
    int m0, int n0, int K, int c, uint32_t sbase, int tid) {
    uint32_t sb = sbase + (c & 1) * 32768;
    int kb = c << 6;
#pragma unroll
    for (int it = 0; it < 4; it++) {
        int idx = it * 256 + tid;
        int row = idx >> 3, cc = idx & 7;
        uint32_t dst = SW128((uint32_t)(row * 128 + cc * 16));
        cp16(sb + dst,         A + (size_t)(m0 + row) * K + kb + cc * 8);
        cp16(sb + 16384 + dst, B + (size_t)(n0 + row) * K + kb + cc * 8);
    }
    CP_COMMIT();
}

__global__ __launch_bounds__(256)
void hmma_gemm_f16(const __half* __restrict__ A, const __half* __restrict__ B,
                   const float* __restrict__ b1, const float* __restrict__ b2,
                   float* __restrict__ C, int N, int K) {
    extern __shared__ char dsm[];
    uint32_t raw = smem_u32(dsm);
    uint32_t sbase = (raw + 1023) & ~1023u;

    int tid = threadIdx.x, wid = tid >> 5, lane = tid & 31;
    int m0 = blockIdx.x << 7, n0 = blockIdx.y << 7;
    int NC = K >> 6;

    gemm_load_chunk_f16(A, B, m0, n0, K, 0, sbase, tid);
    gemm_load_chunk_f16(A, B, m0, n0, K, 1, sbase, tid);

    int wm = wid >> 2, wn = wid & 3;
    int mb = wm * 64, nb = wn * 32;

    float acc[4][4][4];
#pragma unroll
    for (int i = 0; i < 4; i++)
#pragma unroll
        for (int j = 0; j < 4; j++)
#pragma unroll
            for (int q = 0; q < 4; q++) acc[i][j][q] = 0.f;

    int a_r = mb + (lane & 15);
    int a_cb = lane >> 4;
    int b_r = nb + (lane & 7) + ((lane >> 4) << 3);
    int b_cb = (lane >> 3) & 1;

    for (int c = 0; c < NC; c++) {
        if (c + 1 < NC) { CP_WAIT(1); } else { CP_WAIT(0); }
        __syncthreads();
        uint32_t sb = sbase + (c & 1) * 32768;
#pragma unroll
        for (int kt = 0; kt < 4; kt++) {
            unsigned ah[4][4], bh[2][4];
#pragma unroll
            for (int mt = 0; mt < 4; mt++) {
                int r = a_r + mt * 16;
                uint32_t off = (uint32_t)(r * 128)
                             + ((((uint32_t)(kt * 2 + a_cb)) ^ ((uint32_t)r & 7)) << 4);
                ldsm_x4(ah[mt], sb + off);
            }
#pragma unroll
            for (int nt2 = 0; nt2 < 2; nt2++) {
                int r = b_r + nt2 * 16;
                uint32_t off = (uint32_t)(r * 128)
                             + ((((uint32_t)(kt * 2 + b_cb)) ^ ((uint32_t)r & 7)) << 4);
                ldsm_x4(bh[nt2], sb + 16384 + off);
            }
#pragma unroll
            for (int mt = 0; mt < 4; mt++)
#pragma unroll
                for (int nt = 0; nt < 4; nt++)
                    mma_f16h(acc[mt][nt], ah[mt], &bh[nt >> 1][(nt & 1) * 2]);
        }
        __syncthreads();
        if (c + 2 < NC)
            gemm_load_chunk_f16(A, B, m0, n0, K, c + 2, sbase, tid);
    }

    int er = lane >> 2;
    int ec = (lane & 3) << 1;
#pragma unroll
    for (int nt = 0; nt < 4; nt++) {
        int col = n0 + nb + nt * 8 + ec;
        float2 bv = *(const float2*)(b1 + col);
        if (b2) {
            float2 t2 = *(const float2*)(b2 + col);
            bv.x += t2.x; bv.y += t2.y;
        }
#pragma unroll
        for (int mt = 0; mt < 4; mt++) {
            int r0 = m0 + mb + mt * 16 + er;
            *(float2*)(C + (size_t)r0 * N + col) =
                make_float2(acc[mt][nt][0] + bv.x, acc[mt][nt][1] + bv.y);
            *(float2*)(C + (size_t)(r0 + 8) * N + col) =
                make_float2(acc[mt][nt][2] + bv.x, acc[mt][nt][3] + bv.y);
        }
    }
}

// ------------------------- persistent LSTM layer (fp16 recurrence, R14) -----
#define L_W   0                             // fp16 W_hh slice: 16 chunks x 4KB
#define L_H   65536                         // fp16 h tiles:    16 chunks x 2KB
#define L_ST  98304                         // float stage[8][16][33]
#define L_DYN (1024 + 98304 + 16896)

__global__ __launch_bounds__(256)
void lstm_layer(const __half* __restrict__ Whh16,
                const float* __restrict__ gatesx,
                const float* __restrict__ h0l, const float* __restrict__ c0l,
                float* __restrict__ hT, float* __restrict__ cT) {
    extern __shared__ char dsm[];
    __shared__ float c_sm[128];
    __shared__ unsigned base_sh;

    uint32_t raw = smem_u32(dsm);
    uint32_t sbase = (raw + 1023) & ~1023u;
    char* smp = dsm + (sbase - raw);
    float* stage = (float*)(smp + L_ST);

    int tid = threadIdx.x, bid = blockIdx.x;
    int w = tid >> 5, lane = tid & 31;

    if (tid == 0) base_sh = g_gen;
    __syncthreads();
    unsigned tgt = base_sh;

    // ---- W_hh fp16 slice load (once per layer) ----
    for (int p = tid * 2; p < tid * 2 + 2; p++) {
        int l = p >> 4, c = p & 15;
        size_t grow = (size_t)((l >> 3) * HIDDEN + bid * 8 + (l & 7)) * HIDDEN + c * 64;
        uint32_t cb = (uint32_t)(c * 4096);
#pragma unroll
        for (int cc = 0; cc < 8; cc++) {
            uint32_t sw = cb + SW128((uint32_t)(l * 128 + cc * 16));
            *(uint4*)(smp + L_W + sw) = *(const uint4*)(Whh16 + grow + cc * 8);
        }
    }

    // ---- init state ----
    if (tid < 128) {
        int gi = bid * 128 + tid;
        g_hf16[0][gi] = __float2half_rn(h0l[gi]);
        c_sm[tid] = c0l[(tid >> 3) * HIDDEN + bid * 8 + (tid & 7)];
    }
    grid_bar(++tgt);

    int a_r  = lane & 15;
    int a_cb = lane >> 4;
    int b_r  = (lane & 7) + ((lane >> 4) << 3);
    int b_cb = (lane >> 3) & 1;
    int er = lane >> 2, ec = (lane & 3) << 1;

    int pb = tid >> 3, pc = tid & 7;
    int colp = bid * 8 + pc;

    for (int t = 0; t < SEQ; t++) {
        const __half* hf = g_hf16[t & 1];

        // ---- prefetch gatesx (independent of h) ----
        float gx0 = 0.f, gx1 = 0.f, gx2 = 0.f, gx3 = 0.f;
        if (tid < 128) {
            size_t gb = (size_t)(pb * SEQ + t) * GATES + colp;
            gx0 = __ldg(gatesx + gb);
            gx1 = __ldg(gatesx + gb + 1024);
            gx2 = __ldg(gatesx + gb + 2048);
            gx3 = __ldg(gatesx + gb + 3072);
        }

        // ---- fill h tiles (fp16): 8 cp16 per thread, block-wide ----
#pragma unroll
        for (int u = 0; u < 8; u++) {
            int idx = u * 256 + tid;
            int c   = idx >> 7;
            int rem = idx & 127;
            int row = rem >> 3;
            int cc  = rem & 7;
            uint32_t dst = sbase + L_H + (uint32_t)(c * 2048)
                         + SW128((uint32_t)(row * 128 + cc * 16));
            cp16(dst, hf + row * 1024 + c * 64 + cc * 8);
        }
        CP_COMMIT();
        CP_WAIT(0);
        __syncthreads();

        // ---- MMA: warp w handles k-chunks {2w, 2w+1} ----
        float acc[4][4];
#pragma unroll
        for (int i = 0; i < 4; i++)
#pragma unroll
            for (int q = 0; q < 4; q++) acc[i][q] = 0.f;

#pragma unroll
        for (int ci = 0; ci < 2; ci++) {
            int c = 2 * w + ci;
            uint32_t hb = sbase + L_H + (uint32_t)(c * 2048);
            uint32_t wb = sbase + L_W + (uint32_t)(c * 4096);
#pragma unroll
            for (int kt = 0; kt < 4; kt++) {
                unsigned ah[4], bh[2][4];
                {
                    uint32_t off = (uint32_t)(a_r * 128)
                                 + ((((uint32_t)(kt * 2 + a_cb)) ^ ((uint32_t)a_r & 7)) << 4);
                    ldsm_x4(ah, hb + off);
                }
#pragma unroll
                for (int nt2 = 0; nt2 < 2; nt2++) {
                    int r = b_r + nt2 * 16;
                    uint32_t off = (uint32_t)(r * 128)
                                 + ((((uint32_t)(kt * 2 + b_cb)) ^ ((uint32_t)r & 7)) << 4);
                    ldsm_x4(bh[nt2], wb + off);
                }
#pragma unroll
                for (int nt = 0; nt < 4; nt++)
                    mma_f16h(acc[nt], ah, &bh[nt >> 1][(nt & 1) * 2]);
            }
        }

        // ---- stage partials ----
#pragma unroll
        for (int nt = 0; nt < 4; nt++) {
            int col = nt * 8 + ec;
            stage[w * 528 + er * 33 + col]           = acc[nt][0];
            stage[w * 528 + er * 33 + col + 1]       = acc[nt][1];
            stage[w * 528 + (er + 8) * 33 + col]     = acc[nt][2];
            stage[w * 528 + (er + 8) * 33 + col + 1] = acc[nt][3];
        }
        __syncthreads();

        // ---- fused reduce + pointwise (128 threads, fast math) ----
        if (tid < 128) {
            float gi = gx0, gf = gx1, gg = gx2, go = gx3;
#pragma unroll
            for (int q = 0; q < 8; q++) {
                const float* sp = stage + q * 528 + pb * 33;
                gi += sp[pc];
                gf += sp[8 + pc];
                gg += sp[16 + pc];
                go += sp[24 + pc];
            }
            float si = 1.f / (1.f + __expf(-gi));
            float sf = 1.f / (1.f + __expf(-gf));
            float tg = 2.f / (1.f + __expf(-2.f * gg)) - 1.f;
            float so = 1.f / (1.f + __expf(-go));
            float cn = sf * c_sm[tid] + si * tg;
            c_sm[tid] = cn;
            float hn = so * (2.f / (1.f + __expf(-2.f * cn)) - 1.f);

            __half h16 = __float2half_rn(hn);
            int sidx = pb * HIDDEN + colp;
            g_hf16[(t + 1) & 1][sidx] = h16;
            g_hist16[(size_t)(pb * SEQ + t) * HIDDEN + colp] = h16;
            if (t == SEQ - 1) hT[sidx] = hn;
        }
        grid_bar(++tgt);
    }
    if (tid < 128)
        cT[pb * HIDDEN + colp] = c_sm[tid];
}

// ------------------------- launch -------------------------
extern "C" void kernel_launch(void* const* d_in, const int* in_sizes, int n_in,
                              void* d_out, int out_size) {
    const int*   x     = (const int*)  d_in[0];
    const float* h0    = (const float*)d_in[1];
    const float* c0    = (const float*)d_in[2];
    const float* emb   = (const float*)d_in[3];
    const float* W_ih0 = (const float*)d_in[4];
    const float* W_hh0 = (const float*)d_in[5];
    const float* b_ih0 = (const float*)d_in[6];
    const float* b_hh0 = (const float*)d_in[7];
    const float* W_ih1 = (const float*)d_in[8];
    const float* W_hh1 = (const float*)d_in[9];
    const float* b_ih1 = (const float*)d_in[10];
    const float* b_hh1 = (const float*)d_in[11];
    const float* fc_W  = (const float*)d_in[12];
    const float* fc_b  = (const float*)d_in[13];

    float* out    = (float*)d_out;
    float* logits = out;
    float* hT     = out + (size_t)MROWS * VOCAB;
    float* cT     = hT + 2 * BATCH * HIDDEN;

    float* p_gatesx;
    __half *p_hist, *p_w16, *p_whh16;
    cudaGetSymbolAddress((void**)&p_gatesx, g_gatesx);
    cudaGetSymbolAddress((void**)&p_hist, g_hist16);
    cudaGetSymbolAddress((void**)&p_w16, g_w16);
    cudaGetSymbolAddress((void**)&p_whh16, g_whh16);

    const int GSM16 = 1024 + 2 * 32768;
    cudaFuncSetAttribute(hmma_gemm_f16, cudaFuncAttributeMaxDynamicSharedMemorySize, GSM16);
    cudaFuncSetAttribute(lstm_layer, cudaFuncAttributeMaxDynamicSharedMemorySize, L_DYN);

    const int SH = BATCH * HIDDEN;

    // layer 0
    embed_cvt16<<<MROWS * 64 / 256, 256>>>(x, emb, p_hist);
    cvt_f16<<<GATES * EMBED / 8 / 256, 256>>>(W_ih0, p_w16, GATES * EMBED / 8);
    cvt_f16<<<GATES * HIDDEN / 8 / 256, 256>>>(W_hh0, p_whh16, GATES * HIDDEN / 8);
    hmma_gemm_f16<<<dim3(MROWS / 128, GATES / 128), 256, GSM16>>>(
        p_hist, p_w16, b_ih0, b_hh0, p_gatesx, GATES, EMBED);
    lstm_layer<<<NBLK, 256, L_DYN>>>(p_whh16, p_gatesx, h0, c0, hT, cT);

    // layer 1 (lstm0 wrote fp16 history into g_hist16)
    cvt_f16<<<GATES * HIDDEN / 8 / 256, 256>>>(W_ih1, p_w16, GATES * HIDDEN / 8);
    cvt_f16<<<GATES * HIDDEN / 8 / 256, 256>>>(W_hh1, p_whh16, GATES * HIDDEN / 8);
    hmma_gemm_f16<<<dim3(MROWS / 128, GATES / 128), 256, GSM16>>>(
        p_hist, p_w16, b_ih1, b_hh1, p_gatesx, GATES, HIDDEN);
    lstm_layer<<<NBLK, 256, L_DYN>>>(p_whh16, p_gatesx, h0 + SH, c0 + SH,
                                     hT + SH, cT + SH);

    // FC head (lstm1 wrote fp16 history into g_hist16)
    cvt_f16<<<VOCAB * HIDDEN / 8 / 256, 256>>>(fc_W, p_w16, VOCAB * HIDDEN / 8);
    hmma_gemm_f16<<<dim3(MROWS / 128, VOCAB / 128), 256, GSM16>>>(
        p_hist, p_w16, fc_b, nullptr, logits, VOCAB, HIDDEN);
}

// round 16
// speedup vs baseline: 1.2410x; 1.0418x over previous
#include <cuda_runtime.h>
#include <cuda_fp16.h>
#include <cstdint>

#define BATCH   16
#define SEQ     256
#define EMBED   512
#define HIDDEN  1024
#define GATES   (4 * HIDDEN)
#define VOCAB   32000
#define MROWS   (BATCH * SEQ)
#define NBLK    128
typedef unsigned long long ull;

// ------------------------- scratch (device globals) -------------------------
__device__ float g_gatesx[MROWS * GATES];             // 64 MB preacts
__device__ __half g_hist16[MROWS * HIDDEN];           //  8 MB A-history (fp16)
__device__ __half g_w16[(size_t)VOCAB * HIDDEN];      // 64 MB weight buffer (fp16)
__device__ __half g_whh16[GATES * HIDDEN];            //  8 MB W_hh (fp16)
__device__ __half g_hf16[2][BATCH * HIDDEN];          // recurrent h state, fp16
__device__ unsigned g_cnt;
__device__ unsigned g_gen;

// ------------------------- HMMA / smem helpers (plain sm_103-safe) ----------
__device__ __forceinline__ uint32_t smem_u32(const void* p) {
    uint32_t a;
    asm("{ .reg .u64 t; cvta.to.shared.u64 t, %1; cvt.u32.u64 %0, t; }" : "=r"(a) : "l"(p));
    return a;
}
__device__ __forceinline__ void mma_f16h(float* d, const unsigned* a, const unsigned* b) {
    asm volatile("mma.sync.aligned.m16n8k16.row.col.f32.f16.f16.f32 "
        "{%0,%1,%2,%3}, {%4,%5,%6,%7}, {%8,%9}, {%0,%1,%2,%3};"
        : "+f"(d[0]), "+f"(d[1]), "+f"(d[2]), "+f"(d[3])
        : "r"(a[0]), "r"(a[1]), "r"(a[2]), "r"(a[3]), "r"(b[0]), "r"(b[1]));
}
__device__ __forceinline__ void ldsm_x4(unsigned* r, uint32_t addr) {
    asm volatile("ldmatrix.sync.aligned.m8n8.x4.shared.b16 {%0,%1,%2,%3}, [%4];"
        : "=r"(r[0]), "=r"(r[1]), "=r"(r[2]), "=r"(r[3]) : "r"(addr));
}
__device__ __forceinline__ void cp16(uint32_t dst, const void* src) {
    asm volatile("cp.async.cg.shared.global [%0], [%1], 16;" :: "r"(dst), "l"(src));
}
#define CP_COMMIT()  asm volatile("cp.async.commit_group;" ::: "memory")
#define CP_WAIT(n)   asm volatile("cp.async.wait_group %0;" :: "n"(n) : "memory")
#define SW128(o) ((o) ^ (((o) >> 3) & 0x70))

// ------------------------- grid barrier v2 (acq/rel, no full fences) --------
__device__ __forceinline__ void grid_bar(unsigned target) {
    __syncthreads();
    if (threadIdx.x == 0) {
        unsigned old;
        asm volatile("atom.add.acq_rel.gpu.global.u32 %0, [%1], 1;"
                     : "=r"(old) : "l"(&g_cnt) : "memory");
        if (old == NBLK - 1) {
            asm volatile("st.relaxed.gpu.global.u32 [%0], %1;"
                         :: "l"(&g_cnt), "r"(0u) : "memory");
            asm volatile("st.release.gpu.global.u32 [%0], %1;"
                         :: "l"(&g_gen), "r"(target) : "memory");
        } else {
            unsigned g;
            do {
                asm volatile("ld.acquire.gpu.global.u32 %0, [%1];"
                             : "=r"(g) : "l"(&g_gen) : "memory");
            } while ((int)(g - target) < 0);
        }
    }
    __syncthreads();
}

// ------------------------- fp32 -> fp16 convert ------------------------------
__global__ void cvt_f16(const float* __restrict__ src, __half* __restrict__ dst, int n8) {
    int i = blockIdx.x * 256 + threadIdx.x;
    if (i >= n8) return;
    const float4* s = (const float4*)src + 2 * (size_t)i;
    float4 v0 = s[0], v1 = s[1];
    __half2 p0 = __floats2half2_rn(v0.x, v0.y);
    __half2 p1 = __floats2half2_rn(v0.z, v0.w);
    __half2 p2 = __floats2half2_rn(v1.x, v1.y);
    __half2 p3 = __floats2half2_rn(v1.z, v1.w);
    uint4 o;
    o.x = *(unsigned*)&p0; o.y = *(unsigned*)&p1;
    o.z = *(unsigned*)&p2; o.w = *(unsigned*)&p3;
    ((uint4*)dst)[i] = o;
}

__global__ void embed_cvt16(const int* __restrict__ x, const float* __restrict__ emb,
                            __half* __restrict__ dst) {
    int idx = blockIdx.x * 256 + threadIdx.x;
    int row = idx >> 6;
    int e8  = idx & 63;
    const float4* s = (const float4*)(emb + ((size_t)x[row] << 9)) + 2 * e8;
    float4 v0 = s[0], v1 = s[1];
    __half2 p0 = __floats2half2_rn(v0.x, v0.y);
    __half2 p1 = __floats2half2_rn(v0.z, v0.w);
    __half2 p2 = __floats2half2_rn(v1.x, v1.y);
    __half2 p3 = __floats2half2_rn(v1.z, v1.w);
    uint4 o;
    o.x = *(unsigned*)&p0; o.y = *(unsigned*)&p1;
    o.z = *(unsigned*)&p2; o.w = *(unsigned*)&p3;
    ((uint4*)dst)[idx] = o;
}

// ------------------------- HMMA GEMM fp16, 128x128 tile (verified R15) ------
__device__ __forceinline__ void gemm_load_chunk_f16(
    const __half* A, const __half* B,
    int m0, int n0, int K, int c, uint32_t sbase, int tid) {
    uint32_t sb = sbase + (c & 1) * 32768;
    int kb = c << 6;
#pragma unroll
    for (int it = 0; it < 4; it++) {
        int idx = it * 256 + tid;
        int row = idx >> 3, cc = idx & 7;
        uint32_t dst = SW128((uint32_t)(row * 128 + cc * 16));
        cp16(sb + dst,         A + (size_t)(m0 + row) * K + kb + cc * 8);
        cp16(sb + 16384 + dst, B + (size_t)(n0 + row) * K + kb + cc * 8);
    }
    CP_COMMIT();
}

__global__ __launch_bounds__(256)
void hmma_gemm_f16(const __half* __restrict__ A, const __half* __restrict__ B,
                   const float* __restrict__ b1, const float* __restrict__ b2,
                   float* __restrict__ C, int N, int K) {
    extern __shared__ char dsm[];
    uint32_t raw = smem_u32(dsm);
    uint32_t sbase = (raw + 1023) & ~1023u;

    int tid = threadIdx.x, wid = tid >> 5, lane = tid & 31;
    int m0 = blockIdx.x << 7, n0 = blockIdx.y << 7;
    int NC = K >> 6;

    gemm_load_chunk_f16(A, B, m0, n0, K, 0, sbase, tid);
    gemm_load_chunk_f16(A, B, m0, n0, K, 1, sbase, tid);

    int wm = wid >> 2, wn = wid & 3;
    int mb = wm * 64, nb = wn * 32;

    float acc[4][4][4];
#pragma unroll
    for (int i = 0; i < 4; i++)
#pragma unroll
        for (int j = 0; j < 4; j++)
#pragma unroll
            for (int q = 0; q < 4; q++) acc[i][j][q] = 0.f;

    int a_r = mb + (lane & 15);
    int a_cb = lane >> 4;
    int b_r = nb + (lane & 7) + ((lane >> 4) << 3);
    int b_cb = (lane >> 3) & 1;

    for (int c = 0; c < NC; c++) {
        if (c + 1 < NC) { CP_WAIT(1); } else { CP_WAIT(0); }
        __syncthreads();
        uint32_t sb = sbase + (c & 1) * 32768;
#pragma unroll
        for (int kt = 0; kt < 4; kt++) {
            unsigned ah[4][4], bh[2][4];
#pragma unroll
            for (int mt = 0; mt < 4; mt++) {
                int r = a_r + mt * 16;
                uint32_t off = (uint32_t)(r * 128)
                             + ((((uint32_t)(kt * 2 + a_cb)) ^ ((uint32_t)r & 7)) << 4);
                ldsm_x4(ah[mt], sb + off);
            }
#pragma unroll
            for (int nt2 = 0; nt2 < 2; nt2++) {
                int r = b_r + nt2 * 16;
                uint32_t off = (uint32_t)(r * 128)
                             + ((((uint32_t)(kt * 2 + b_cb)) ^ ((uint32_t)r & 7)) << 4);
                ldsm_x4(bh[nt2], sb + 16384 + off);
            }
#pragma unroll
            for (int mt = 0; mt < 4; mt++)
#pragma unroll
                for (int nt = 0; nt < 4; nt++)
                    mma_f16h(acc[mt][nt], ah[mt], &bh[nt >> 1][(nt & 1) * 2]);
        }
        __syncthreads();
        if (c + 2 < NC)
            gemm_load_chunk_f16(A, B, m0, n0, K, c + 2, sbase, tid);
    }

    int er = lane >> 2;
    int ec = (lane & 3) << 1;
#pragma unroll
    for (int nt = 0; nt < 4; nt++) {
        int col = n0 + nb + nt * 8 + ec;
        float2 bv = *(const float2*)(b1 + col);
        if (b2) {
            float2 t2 = *(const float2*)(b2 + col);
            bv.x += t2.x; bv.y += t2.y;
        }
#pragma unroll
        for (int mt = 0; mt < 4; mt++) {
            int r0 = m0 + mb + mt * 16 + er;
            *(float2*)(C + (size_t)r0 * N + col) =
                make_float2(acc[mt][nt][0] + bv.x, acc[mt][nt][1] + bv.y);
            *(float2*)(C + (size_t)(r0 + 8) * N + col) =
                make_float2(acc[mt][nt][2] + bv.x, acc[mt][nt][3] + bv.y);
        }
    }
}

// ------------------------- HMMA GEMM fp16, 128x256 tile (FC head) -----------
// 8 warps as 2m x 4n -> warp tile 64x64; 32 MMA per 8 ldsm per kt.
// smem: 2 x (A 16KB + B 32KB) = 96KB.
__device__ __forceinline__ void gemm_load_chunk_w256(
    const __half* A, const __half* B,
    int m0, int n0, int K, int c, uint32_t sbase, int tid) {
    uint32_t sb = sbase + (c & 1) * 49152;
    int kb = c << 6;
#pragma unroll
    for (int it = 0; it < 12; it++) {
        int idx = it * 256 + tid;               // 0..3071
        int row = idx >> 3, cc = idx & 7;
        if (row < 128) {
            uint32_t dst = SW128((uint32_t)(row * 128 + cc * 16));
            cp16(sb + dst, A + (size_t)(m0 + row) * K + kb + cc * 8);
        } else {
            int r = row - 128;
            uint32_t dst = SW128((uint32_t)(r * 128 + cc * 16));
            cp16(sb + 16384 + dst, B + (size_t)(n0 + r) * K + kb + cc * 8);
        }
    }
    CP_COMMIT();
}

__global__ __launch_bounds__(256)
void hmma_gemm_w256(const __half* __restrict__ A, const __half* __restrict__ B,
                    const float* __restrict__ b1,
                    float* __restrict__ C, int N, int K) {
    extern __shared__ char dsm[];
    uint32_t raw = smem_u32(dsm);
    uint32_t sbase = (raw + 1023) & ~1023u;

    int tid = threadIdx.x, wid = tid >> 5, lane = tid & 31;
    int m0 = blockIdx.x << 7, n0 = blockIdx.y << 8;
    int NC = K >> 6;

    gemm_load_chunk_w256(A, B, m0, n0, K, 0, sbase, tid);
    gemm_load_chunk_w256(A, B, m0, n0, K, 1, sbase, tid);

    int wm = wid >> 2, wn = wid & 3;     // 2 x 4 warp grid
    int mb = wm * 64, nb = wn * 64;

    float acc[4][8][4];
#pragma unroll
    for (int i = 0; i < 4; i++)
#pragma unroll
        for (int j = 0; j < 8; j++)
#pragma unroll
            for (int q = 0; q < 4; q++) acc[i][j][q] = 0.f;

    int a_r = mb + (lane & 15);
    int a_cb = lane >> 4;
    int b_r = nb + (lane & 7) + ((lane >> 4) << 3);
    int b_cb = (lane >> 3) & 1;

    for (int c = 0; c < NC; c++) {
        if (c + 1 < NC) { CP_WAIT(1); } else { CP_WAIT(0); }
        __syncthreads();
        uint32_t sb = sbase + (c & 1) * 49152;
#pragma unroll
        for (int kt = 0; kt < 4; kt++) {
            unsigned ah[4][4], bh[4][4];
#pragma unroll
            for (int mt = 0; mt < 4; mt++) {
                int r = a_r + mt * 16;
                uint32_t off = (uint32_t)(r * 128)
                             + ((((uint32_t)(kt * 2 + a_cb)) ^ ((uint32_t)r & 7)) << 4);
                ldsm_x4(ah[mt], sb + off);
            }
#pragma unroll
            for (int nt2 = 0; nt2 < 4; nt2++) {
                int r = b_r + nt2 * 16;
                uint32_t off = (uint32_t)(r * 128)
                             + ((((uint32_t)(kt * 2 + b_cb)) ^ ((uint32_t)r & 7)) << 4);
                ldsm_x4(bh[nt2], sb + 16384 + off);
            }
#pragma unroll
            for (int mt = 0; mt < 4; mt++)
#pragma unroll
                for (int nt = 0; nt < 8; nt++)
                    mma_f16h(acc[mt][nt], ah[mt], &bh[nt >> 1][(nt & 1) * 2]);
        }
        __syncthreads();
        if (c + 2 < NC)
            gemm_load_chunk_w256(A, B, m0, n0, K, c + 2, sbase, tid);
    }

    int er = lane >> 2;
    int ec = (lane & 3) << 1;
#pragma unroll
    for (int nt = 0; nt < 8; nt++) {
        int col = n0 + nb + nt * 8 + ec;
        float2 bv = *(const float2*)(b1 + col);
#pragma unroll
        for (int mt = 0; mt < 4; mt++) {
            int r0 = m0 + mb + mt * 16 + er;
            *(float2*)(C + (size_t)r0 * N + col) =
                make_float2(acc[mt][nt][0] + bv.x, acc[mt][nt][1] + bv.y);
            *(float2*)(C + (size_t)(r0 + 8) * N + col) =
                make_float2(acc[mt][nt][2] + bv.x, acc[mt][nt][3] + bv.y);
        }
    }
}

// ------------------------- persistent LSTM layer (fp16, barrier v2) ---------
#define L_W   0                             // fp16 W_hh slice: 16 chunks x 4KB
#define L_H   65536                         // fp16 h tiles:    16 chunks x 2KB
#define L_ST  98304                         // float stage[8][16][33]
#define L_DYN (1024 + 98304 + 16896)

__global__ __launch_bounds__(256)
void lstm_layer(const __half* __restrict__ Whh16,
                const float* __restrict__ gatesx,
                const float* __restrict__ h0l, const float* __restrict__ c0l,
                float* __restrict__ hT, float* __restrict__ cT) {
    extern __shared__ char dsm[];
    __shared__ float c_sm[128];
    __shared__ unsigned base_sh;

    uint32_t raw = smem_u32(dsm);
    uint32_t sbase = (raw + 1023) & ~1023u;
    char* smp = dsm + (sbase - raw);
    float* stage = (float*)(smp + L_ST);

    int tid = threadIdx.x, bid = blockIdx.x;
    int w = tid >> 5, lane = tid & 31;

    if (tid == 0) {
        unsigned g;
        asm volatile("ld.acquire.gpu.global.u32 %0, [%1];" : "=r"(g) : "l"(&g_gen));
        base_sh = g;
    }
    __syncthreads();
    unsigned tgt = base_sh;

    // ---- W_hh fp16 slice load (once per layer) ----
    for (int p = tid * 2; p < tid * 2 + 2; p++) {
        int l = p >> 4, c = p & 15;
        size_t grow = (size_t)((l >> 3) * HIDDEN + bid * 8 + (l & 7)) * HIDDEN + c * 64;
        uint32_t cb = (uint32_t)(c * 4096);
#pragma unroll
        for (int cc = 0; cc < 8; cc++) {
            uint32_t sw = cb + SW128((uint32_t)(l * 128 + cc * 16));
            *(uint4*)(smp + L_W + sw) = *(const uint4*)(Whh16 + grow + cc * 8);
        }
    }

    // ---- init state ----
    if (tid < 128) {
        int gi = bid * 128 + tid;
        g_hf16[0][gi] = __float2half_rn(h0l[gi]);
        c_sm[tid] = c0l[(tid >> 3) * HIDDEN + bid * 8 + (tid & 7)];
    }
    grid_bar(++tgt);

    int a_r  = lane & 15;
    int a_cb = lane >> 4;
    int b_r  = (lane & 7) + ((lane >> 4) << 3);
    int b_cb = (lane >> 3) & 1;
    int er = lane >> 2, ec = (lane & 3) << 1;

    int pb = tid >> 3, pc = tid & 7;
    int colp = bid * 8 + pc;

    for (int t = 0; t < SEQ; t++) {
        const __half* hf = g_hf16[t & 1];

        // ---- prefetch gatesx (independent of h) ----
        float gx0 = 0.f, gx1 = 0.f, gx2 = 0.f, gx3 = 0.f;
        if (tid < 128) {
            size_t gb = (size_t)(pb * SEQ + t) * GATES + colp;
            gx0 = __ldg(gatesx + gb);
            gx1 = __ldg(gatesx + gb + 1024);
            gx2 = __ldg(gatesx + gb + 2048);
            gx3 = __ldg(gatesx + gb + 3072);
        }

        // ---- fill h tiles (fp16): 8 cp16 per thread, block-wide ----
#pragma unroll
        for (int u = 0; u < 8; u++) {
            int idx = u * 256 + tid;
            int c   = idx >> 7;
            int rem = idx & 127;
            int row = rem >> 3;
            int cc  = rem & 7;
            uint32_t dst = sbase + L_H + (uint32_t)(c * 2048)
                         + SW128((uint32_t)(row * 128 + cc * 16));
            cp16(dst, hf + row * 1024 + c * 64 + cc * 8);
        }
        CP_COMMIT();
        CP_WAIT(0);
        __syncthreads();

        // ---- MMA: warp w handles k-chunks {2w, 2w+1} ----
        float acc[4][4];
#pragma unroll
        for (int i = 0; i < 4; i++)
#pragma unroll
            for (int q = 0; q < 4; q++) acc[i][q] = 0.f;

#pragma unroll
        for (int ci = 0; ci < 2; ci++) {
            int c = 2 * w + ci;
            uint32_t hb = sbase + L_H + (uint32_t)(c * 2048);
            uint32_t wb = sbase + L_W + (uint32_t)(c * 4096);
#pragma unroll
            for (int kt = 0; kt < 4; kt++) {
                unsigned ah[4], bh[2][4];
                {
                    uint32_t off = (uint32_t)(a_r * 128)
                                 + ((((uint32_t)(kt * 2 + a_cb)) ^ ((uint32_t)a_r & 7)) << 4);
                    ldsm_x4(ah, hb + off);
                }
#pragma unroll
                for (int nt2 = 0; nt2 < 2; nt2++) {
                    int r = b_r + nt2 * 16;
                    uint32_t off = (uint32_t)(r * 128)
                                 + ((((uint32_t)(kt * 2 + b_cb)) ^ ((uint32_t)r & 7)) << 4);
                    ldsm_x4(bh[nt2], wb + off);
                }
#pragma unroll
                for (int nt = 0; nt < 4; nt++)
                    mma_f16h(acc[nt], ah, &bh[nt >> 1][(nt & 1) * 2]);
            }
        }

        // ---- stage partials ----
#pragma unroll
        for (int nt = 0; nt < 4; nt++) {
            int col = nt * 8 + ec;
            stage[w * 528 + er * 33 + col]           = acc[nt][0];
            stage[w * 528 + er * 33 + col + 1]       = acc[nt][1];
            stage[w * 528 + (er + 8) * 33 + col]     = acc[nt][2];
            stage[w * 528 + (er + 8) * 33 + col + 1] = acc[nt][3];
        }
        __syncthreads();

        // ---- fused reduce + pointwise (128 threads, fast math) ----
        if (tid < 128) {
            float gi = gx0, gf = gx1, gg = gx2, go = gx3;
#pragma unroll
            for (int q = 0; q < 8; q++) {
                const float* sp = stage + q * 528 + pb * 33;
                gi += sp[pc];
                gf += sp[8 + pc];
                gg += sp[16 + pc];
                go += sp[24 + pc];
            }
            float si = 1.f / (1.f + __expf(-gi));
            float sf = 1.f / (1.f + __expf(-gf));
            float tg = 2.f / (1.f + __expf(-2.f * gg)) - 1.f;
            float so = 1.f / (1.f + __expf(-go));
            float cn = sf * c_sm[tid] + si * tg;
            c_sm[tid] = cn;
            float hn = so * (2.f / (1.f + __expf(-2.f * cn)) - 1.f);

            __half h16 = __float2half_rn(hn);
            int sidx = pb * HIDDEN + colp;
            g_hf16[(t + 1) & 1][sidx] = h16;
            g_hist16[(size_t)(pb * SEQ + t) * HIDDEN + colp] = h16;
            if (t == SEQ - 1) hT[sidx] = hn;
        }
        grid_bar(++tgt);
    }
    if (tid < 128)
        cT[pb * HIDDEN + colp] = c_sm[tid];
}

// ------------------------- launch -------------------------
extern "C" void kernel_launch(void* const* d_in, const int* in_sizes, int n_in,
                              void* d_out, int out_size) {
    const int*   x     = (const int*)  d_in[0];
    const float* h0    = (const float*)d_in[1];
    const float* c0    = (const float*)d_in[2];
    const float* emb   = (const float*)d_in[3];
    const float* W_ih0 = (const float*)d_in[4];
    const float* W_hh0 = (const float*)d_in[5];
    const float* b_ih0 = (const float*)d_in[6];
    const float* b_hh0 = (const float*)d_in[7];
    const float* W_ih1 = (const float*)d_in[8];
    const float* W_hh1 = (const float*)d_in[9];
    const float* b_ih1 = (const float*)d_in[10];
    const float* b_hh1 = (const float*)d_in[11];
    const float* fc_W  = (const float*)d_in[12];
    const float* fc_b  = (const float*)d_in[13];

    float* out    = (float*)d_out;
    float* logits = out;
    float* hT     = out + (size_t)MROWS * VOCAB;
    float* cT     = hT + 2 * BATCH * HIDDEN;

    float* p_gatesx;
    __half *p_hist, *p_w16, *p_whh16;
    cudaGetSymbolAddress((void**)&p_gatesx, g_gatesx);
    cudaGetSymbolAddress((void**)&p_hist, g_hist16);
    cudaGetSymbolAddress((void**)&p_w16, g_w16);
    cudaGetSymbolAddress((void**)&p_whh16, g_whh16);

    const int GSM16 = 1024 + 2 * 32768;
    const int GSM256 = 1024 + 2 * 49152;
    cudaFuncSetAttribute(hmma_gemm_f16, cudaFuncAttributeMaxDynamicSharedMemorySize, GSM16);
    cudaFuncSetAttribute(hmma_gemm_w256, cudaFuncAttributeMaxDynamicSharedMemorySize, GSM256);
    cudaFuncSetAttribute(lstm_layer, cudaFuncAttributeMaxDynamicSharedMemorySize, L_DYN);

    const int SH = BATCH * HIDDEN;

    // layer 0
    embed_cvt16<<<MROWS * 64 / 256, 256>>>(x, emb, p_hist);
    cvt_f16<<<GATES * EMBED / 8 / 256, 256>>>(W_ih0, p_w16, GATES * EMBED / 8);
    cvt_f16<<<GATES * HIDDEN / 8 / 256, 256>>>(W_hh0, p_whh16, GATES * HIDDEN / 8);
    hmma_gemm_f16<<<dim3(MROWS / 128, GATES / 128), 256, GSM16>>>(
        p_hist, p_w16, b_ih0, b_hh0, p_gatesx, GATES, EMBED);
    lstm_layer<<<NBLK, 256, L_DYN>>>(p_whh16, p_gatesx, h0, c0, hT, cT);

    // layer 1 (lstm0 wrote fp16 history into g_hist16)
    cvt_f16<<<GATES * HIDDEN / 8 / 256, 256>>>(W_ih1, p_w16, GATES * HIDDEN / 8);
    cvt_f16<<<GATES * HIDDEN / 8 / 256, 256>>>(W_hh1, p_whh16, GATES * HIDDEN / 8);
    hmma_gemm_f16<<<dim3(MROWS / 128, GATES / 128), 256, GSM16>>>(
        p_hist, p_w16, b_ih1, b_hh1, p_gatesx, GATES, HIDDEN);
    lstm_layer<<<NBLK, 256, L_DYN>>>(p_whh16, p_gatesx, h0 + SH, c0 + SH,
                                     hT + SH, cT + SH);

    // FC head: wide 128x256 tile (lstm1 wrote fp16 history into g_hist16)
    cvt_f16<<<VOCAB * HIDDEN / 8 / 256, 256>>>(fc_W, p_w16, VOCAB * HIDDEN / 8);
    hmma_gemm_w256<<<dim3(MROWS / 128, VOCAB / 256), 256, GSM256>>>(
        p_hist, p_w16, fc_b, logits, VOCAB, HIDDEN);
}

// round 17
// speedup vs baseline: 1.2782x; 1.0300x over previous
#include <cuda_runtime.h>
#include <cuda_fp16.h>
#include <cstdint>

#define BATCH   16
#define SEQ     256
#define EMBED   512
#define HIDDEN  1024
#define GATES   (4 * HIDDEN)
#define VOCAB   32000
#define MROWS   (BATCH * SEQ)
#define NBLK    128
typedef unsigned long long ull;

// ------------------------- scratch (device globals) -------------------------
__device__ float g_gatesx[MROWS * GATES];             // 64 MB preacts
__device__ __half g_hist16[MROWS * HIDDEN];           //  8 MB A-history (fp16)
__device__ __half g_w16[(size_t)VOCAB * HIDDEN];      // 64 MB weight buffer (fp16)
__device__ __half g_whh16[GATES * HIDDEN];            //  8 MB W_hh (fp16)
__device__ __half g_hf16[2][BATCH * HIDDEN];          // recurrent h state, fp16
__device__ unsigned g_cnt;
__device__ unsigned g_gen;

// ------------------------- HMMA / smem helpers (plain sm_103-safe) ----------
__device__ __forceinline__ uint32_t smem_u32(const void* p) {
    uint32_t a;
    asm("{ .reg .u64 t; cvta.to.shared.u64 t, %1; cvt.u32.u64 %0, t; }" : "=r"(a) : "l"(p));
    return a;
}
__device__ __forceinline__ void mma_f16h(float* d, const unsigned* a, const unsigned* b) {
    asm volatile("mma.sync.aligned.m16n8k16.row.col.f32.f16.f16.f32 "
        "{%0,%1,%2,%3}, {%4,%5,%6,%7}, {%8,%9}, {%0,%1,%2,%3};"
        : "+f"(d[0]), "+f"(d[1]), "+f"(d[2]), "+f"(d[3])
        : "r"(a[0]), "r"(a[1]), "r"(a[2]), "r"(a[3]), "r"(b[0]), "r"(b[1]));
}
__device__ __forceinline__ void ldsm_x4(unsigned* r, uint32_t addr) {
    asm volatile("ldmatrix.sync.aligned.m8n8.x4.shared.b16 {%0,%1,%2,%3}, [%4];"
        : "=r"(r[0]), "=r"(r[1]), "=r"(r[2]), "=r"(r[3]) : "r"(addr));
}
__device__ __forceinline__ void cp16(uint32_t dst, const void* src) {
    asm volatile("cp.async.cg.shared.global [%0], [%1], 16;" :: "r"(dst), "l"(src));
}
#define CP_COMMIT()  asm volatile("cp.async.commit_group;" ::: "memory")
#define CP_WAIT(n)   asm volatile("cp.async.wait_group %0;" :: "n"(n) : "memory")
#define SW128(o) ((o) ^ (((o) >> 3) & 0x70))

// ------------------------- grid barrier (acq/rel) ---------------------------
__device__ __forceinline__ void grid_bar(unsigned target) {
    __syncthreads();
    if (threadIdx.x == 0) {
        unsigned old;
        asm volatile("atom.add.acq_rel.gpu.global.u32 %0, [%1], 1;"
                     : "=r"(old) : "l"(&g_cnt) : "memory");
        if (old == NBLK - 1) {
            asm volatile("st.relaxed.gpu.global.u32 [%0], %1;"
                         :: "l"(&g_cnt), "r"(0u) : "memory");
            asm volatile("st.release.gpu.global.u32 [%0], %1;"
                         :: "l"(&g_gen), "r"(target) : "memory");
        } else {
            unsigned g;
            do {
                asm volatile("ld.acquire.gpu.global.u32 %0, [%1];"
                             : "=r"(g) : "l"(&g_gen) : "memory");
            } while ((int)(g - target) < 0);
        }
    }
    __syncthreads();
}

// ------------------------- fp32 -> fp16 convert ------------------------------
__global__ void cvt_f16(const float* __restrict__ src, __half* __restrict__ dst, int n8) {
    int i = blockIdx.x * 256 + threadIdx.x;
    if (i >= n8) return;
    const float4* s = (const float4*)src + 2 * (size_t)i;
    float4 v0 = s[0], v1 = s[1];
    __half2 p0 = __floats2half2_rn(v0.x, v0.y);
    __half2 p1 = __floats2half2_rn(v0.z, v0.w);
    __half2 p2 = __floats2half2_rn(v1.x, v1.y);
    __half2 p3 = __floats2half2_rn(v1.z, v1.w);
    uint4 o;
    o.x = *(unsigned*)&p0; o.y = *(unsigned*)&p1;
    o.z = *(unsigned*)&p2; o.w = *(unsigned*)&p3;
    ((uint4*)dst)[i] = o;
}

__global__ void embed_cvt16(const int* __restrict__ x, const float* __restrict__ emb,
                            __half* __restrict__ dst) {
    int idx = blockIdx.x * 256 + threadIdx.x;
    int row = idx >> 6;
    int e8  = idx & 63;
    const float4* s = (const float4*)(emb + ((size_t)x[row] << 9)) + 2 * e8;
    float4 v0 = s[0], v1 = s[1];
    __half2 p0 = __floats2half2_rn(v0.x, v0.y);
    __half2 p1 = __floats2half2_rn(v0.z, v0.w);
    __half2 p2 = __floats2half2_rn(v1.x, v1.y);
    __half2 p3 = __floats2half2_rn(v1.z, v1.w);
    uint4 o;
    o.x = *(unsigned*)&p0; o.y = *(unsigned*)&p1;
    o.z = *(unsigned*)&p2; o.w = *(unsigned*)&p3;
    ((uint4*)dst)[idx] = o;
}

// ------------------------- HMMA GEMM fp16, 128x128 tile (verified R15) ------
__device__ __forceinline__ void gemm_load_chunk_f16(
    const __half* A, const __half* B,
    int m0, int n0, int K, int c, uint32_t sbase, int tid) {
    uint32_t sb = sbase + (c & 1) * 32768;
    int kb = c << 6;
#pragma unroll
    for (int it = 0; it < 4; it++) {
        int idx = it * 256 + tid;
        int row = idx >> 3, cc = idx & 7;
        uint32_t dst = SW128((uint32_t)(row * 128 + cc * 16));
        cp16(sb + dst,         A + (size_t)(m0 + row) * K + kb + cc * 8);
        cp16(sb + 16384 + dst, B + (size_t)(n0 + row) * K + kb + cc * 8);
    }
    CP_COMMIT();
}

__global__ __launch_bounds__(256)
void hmma_gemm_f16(const __half* __restrict__ A, const __half* __restrict__ B,
                   const float* __restrict__ b1, const float* __restrict__ b2,
                   float* __restrict__ C, int N, int K) {
    extern __shared__ char dsm[];
    uint32_t raw = smem_u32(dsm);
    uint32_t sbase = (raw + 1023) & ~1023u;

    int tid = threadIdx.x, wid = tid >> 5, lane = tid & 31;
    int m0 = blockIdx.x << 7, n0 = blockIdx.y << 7;
    int NC = K >> 6;

    gemm_load_chunk_f16(A, B, m0, n0, K, 0, sbase, tid);
    gemm_load_chunk_f16(A, B, m0, n0, K, 1, sbase, tid);

    int wm = wid >> 2, wn = wid & 3;
    int mb = wm * 64, nb = wn * 32;

    float acc[4][4][4];
#pragma unroll
    for (int i = 0; i < 4; i++)
#pragma unroll
        for (int j = 0; j < 4; j++)
#pragma unroll
            for (int q = 0; q < 4; q++) acc[i][j][q] = 0.f;

    int a_r = mb + (lane & 15);
    int a_cb = lane >> 4;
    int b_r = nb + (lane & 7) + ((lane >> 4) << 3);
    int b_cb = (lane >> 3) & 1;

    for (int c = 0; c < NC; c++) {
        if (c + 1 < NC) { CP_WAIT(1); } else { CP_WAIT(0); }
        __syncthreads();
        uint32_t sb = sbase + (c & 1) * 32768;
#pragma unroll
        for (int kt = 0; kt < 4; kt++) {
            unsigned ah[4][4], bh[2][4];
#pragma unroll
            for (int mt = 0; mt < 4; mt++) {
                int r = a_r + mt * 16;
                uint32_t off = (uint32_t)(r * 128)
                             + ((((uint32_t)(kt * 2 + a_cb)) ^ ((uint32_t)r & 7)) << 4);
                ldsm_x4(ah[mt], sb + off);
            }
#pragma unroll
            for (int nt2 = 0; nt2 < 2; nt2++) {
                int r = b_r + nt2 * 16;
                uint32_t off = (uint32_t)(r * 128)
                             + ((((uint32_t)(kt * 2 + b_cb)) ^ ((uint32_t)r & 7)) << 4);
                ldsm_x4(bh[nt2], sb + 16384 + off);
            }
#pragma unroll
            for (int mt = 0; mt < 4; mt++)
#pragma unroll
                for (int nt = 0; nt < 4; nt++)
                    mma_f16h(acc[mt][nt], ah[mt], &bh[nt >> 1][(nt & 1) * 2]);
        }
        __syncthreads();
        if (c + 2 < NC)
            gemm_load_chunk_f16(A, B, m0, n0, K, c + 2, sbase, tid);
    }

    int er = lane >> 2;
    int ec = (lane & 3) << 1;
#pragma unroll
    for (int nt = 0; nt < 4; nt++) {
        int col = n0 + nb + nt * 8 + ec;
        float2 bv = *(const float2*)(b1 + col);
        if (b2) {
            float2 t2 = *(const float2*)(b2 + col);
            bv.x += t2.x; bv.y += t2.y;
        }
#pragma unroll
        for (int mt = 0; mt < 4; mt++) {
            int r0 = m0 + mb + mt * 16 + er;
            *(float2*)(C + (size_t)r0 * N + col) =
                make_float2(acc[mt][nt][0] + bv.x, acc[mt][nt][1] + bv.y);
            *(float2*)(C + (size_t)(r0 + 8) * N + col) =
                make_float2(acc[mt][nt][2] + bv.x, acc[mt][nt][3] + bv.y);
        }
    }
}

// ------------------------- HMMA GEMM fp16, 128x256 tile (FC head) -----------
__device__ __forceinline__ void gemm_load_chunk_w256(
    const __half* A, const __half* B,
    int m0, int n0, int K, int c, uint32_t sbase, int tid) {
    uint32_t sb = sbase + (c & 1) * 49152;
    int kb = c << 6;
#pragma unroll
    for (int it = 0; it < 12; it++) {
        int idx = it * 256 + tid;
        int row = idx >> 3, cc = idx & 7;
        if (row < 128) {
            uint32_t dst = SW128((uint32_t)(row * 128 + cc * 16));
            cp16(sb + dst, A + (size_t)(m0 + row) * K + kb + cc * 8);
        } else {
            int r = row - 128;
            uint32_t dst = SW128((uint32_t)(r * 128 + cc * 16));
            cp16(sb + 16384 + dst, B + (size_t)(n0 + r) * K + kb + cc * 8);
        }
    }
    CP_COMMIT();
}

__global__ __launch_bounds__(256)
void hmma_gemm_w256(const __half* __restrict__ A, const __half* __restrict__ B,
                    const float* __restrict__ b1,
                    float* __restrict__ C, int N, int K) {
    extern __shared__ char dsm[];
    uint32_t raw = smem_u32(dsm);
    uint32_t sbase = (raw + 1023) & ~1023u;

    int tid = threadIdx.x, wid = tid >> 5, lane = tid & 31;
    int m0 = blockIdx.x << 7, n0 = blockIdx.y << 8;
    int NC = K >> 6;

    gemm_load_chunk_w256(A, B, m0, n0, K, 0, sbase, tid);
    gemm_load_chunk_w256(A, B, m0, n0, K, 1, sbase, tid);

    int wm = wid >> 2, wn = wid & 3;
    int mb = wm * 64, nb = wn * 64;

    float acc[4][8][4];
#pragma unroll
    for (int i = 0; i < 4; i++)
#pragma unroll
        for (int j = 0; j < 8; j++)
#pragma unroll
            for (int q = 0; q < 4; q++) acc[i][j][q] = 0.f;

    int a_r = mb + (lane & 15);
    int a_cb = lane >> 4;
    int b_r = nb + (lane & 7) + ((lane >> 4) << 3);
    int b_cb = (lane >> 3) & 1;

    for (int c = 0; c < NC; c++) {
        if (c + 1 < NC) { CP_WAIT(1); } else { CP_WAIT(0); }
        __syncthreads();
        uint32_t sb = sbase + (c & 1) * 49152;
#pragma unroll
        for (int kt = 0; kt < 4; kt++) {
            unsigned ah[4][4], bh[4][4];
#pragma unroll
            for (int mt = 0; mt < 4; mt++) {
                int r = a_r + mt * 16;
                uint32_t off = (uint32_t)(r * 128)
                             + ((((uint32_t)(kt * 2 + a_cb)) ^ ((uint32_t)r & 7)) << 4);
                ldsm_x4(ah[mt], sb + off);
            }
#pragma unroll
            for (int nt2 = 0; nt2 < 4; nt2++) {
                int r = b_r + nt2 * 16;
                uint32_t off = (uint32_t)(r * 128)
                             + ((((uint32_t)(kt * 2 + b_cb)) ^ ((uint32_t)r & 7)) << 4);
                ldsm_x4(bh[nt2], sb + 16384 + off);
            }
#pragma unroll
            for (int mt = 0; mt < 4; mt++)
#pragma unroll
                for (int nt = 0; nt < 8; nt++)
                    mma_f16h(acc[mt][nt], ah[mt], &bh[nt >> 1][(nt & 1) * 2]);
        }
        __syncthreads();
        if (c + 2 < NC)
            gemm_load_chunk_w256(A, B, m0, n0, K, c + 2, sbase, tid);
    }

    int er = lane >> 2;
    int ec = (lane & 3) << 1;
#pragma unroll
    for (int nt = 0; nt < 8; nt++) {
        int col = n0 + nb + nt * 8 + ec;
        float2 bv = *(const float2*)(b1 + col);
#pragma unroll
        for (int mt = 0; mt < 4; mt++) {
            int r0 = m0 + mb + mt * 16 + er;
            *(float2*)(C + (size_t)r0 * N + col) =
                make_float2(acc[mt][nt][0] + bv.x, acc[mt][nt][1] + bv.y);
            *(float2*)(C + (size_t)(r0 + 8) * N + col) =
                make_float2(acc[mt][nt][2] + bv.x, acc[mt][nt][3] + bv.y);
        }
    }
}

// ------------------------- persistent LSTM layer (W in registers) -----------
// W_hh fragments ldsm'd ONCE into 64 regs/thread before the time loop;
// per-step smem traffic = h fragments only (8 ldsm vs 24).
#define L_W   0                             // fp16 W_hh slice: 16 chunks x 4KB
#define L_H   65536                         // fp16 h tiles:    16 chunks x 2KB
#define L_ST  98304                         // float stage[8][16][33]
#define L_DYN (1024 + 98304 + 16896)

__global__ __launch_bounds__(256)
void lstm_layer(const __half* __restrict__ Whh16,
                const float* __restrict__ gatesx,
                const float* __restrict__ h0l, const float* __restrict__ c0l,
                float* __restrict__ hT, float* __restrict__ cT) {
    extern __shared__ char dsm[];
    __shared__ float c_sm[128];
    __shared__ unsigned base_sh;

    uint32_t raw = smem_u32(dsm);
    uint32_t sbase = (raw + 1023) & ~1023u;
    char* smp = dsm + (sbase - raw);
    float* stage = (float*)(smp + L_ST);

    int tid = threadIdx.x, bid = blockIdx.x;
    int w = tid >> 5, lane = tid & 31;

    if (tid == 0) {
        unsigned g;
        asm volatile("ld.acquire.gpu.global.u32 %0, [%1];" : "=r"(g) : "l"(&g_gen));
        base_sh = g;
    }
    __syncthreads();
    unsigned tgt = base_sh;

    // ---- W_hh fp16 slice load into smem (once) ----
    for (int p = tid * 2; p < tid * 2 + 2; p++) {
        int l = p >> 4, c = p & 15;
        size_t grow = (size_t)((l >> 3) * HIDDEN + bid * 8 + (l & 7)) * HIDDEN + c * 64;
        uint32_t cb = (uint32_t)(c * 4096);
#pragma unroll
        for (int cc = 0; cc < 8; cc++) {
            uint32_t sw = cb + SW128((uint32_t)(l * 128 + cc * 16));
            *(uint4*)(smp + L_W + sw) = *(const uint4*)(Whh16 + grow + cc * 8);
        }
    }

    // ---- init state ----
    if (tid < 128) {
        int gi = bid * 128 + tid;
        g_hf16[0][gi] = __float2half_rn(h0l[gi]);
        c_sm[tid] = c0l[(tid >> 3) * HIDDEN + bid * 8 + (tid & 7)];
    }
    __syncthreads();   // W smem visible to ldsm below

    int a_r  = lane & 15;
    int a_cb = lane >> 4;
    int b_r  = (lane & 7) + ((lane >> 4) << 3);
    int b_cb = (lane >> 3) & 1;
    int er = lane >> 2, ec = (lane & 3) << 1;

    // ---- hoist W fragments into registers (loop-invariant) ----
    unsigned bw[2][4][2][4];
#pragma unroll
    for (int ci = 0; ci < 2; ci++) {
        int c = 2 * w + ci;
        uint32_t wb = sbase + L_W + (uint32_t)(c * 4096);
#pragma unroll
        for (int kt = 0; kt < 4; kt++)
#pragma unroll
            for (int nt2 = 0; nt2 < 2; nt2++) {
                int r = b_r + nt2 * 16;
                uint32_t off = (uint32_t)(r * 128)
                             + ((((uint32_t)(kt * 2 + b_cb)) ^ ((uint32_t)r & 7)) << 4);
                ldsm_x4(bw[ci][kt][nt2], wb + off);
            }
    }
    grid_bar(++tgt);

    int pb = tid >> 3, pc = tid & 7;
    int colp = bid * 8 + pc;

    for (int t = 0; t < SEQ; t++) {
        const __half* hf = g_hf16[t & 1];

        // ---- prefetch gatesx (independent of h) ----
        float gx0 = 0.f, gx1 = 0.f, gx2 = 0.f, gx3 = 0.f;
        if (tid < 128) {
            size_t gb = (size_t)(pb * SEQ + t) * GATES + colp;
            gx0 = __ldg(gatesx + gb);
            gx1 = __ldg(gatesx + gb + 1024);
            gx2 = __ldg(gatesx + gb + 2048);
            gx3 = __ldg(gatesx + gb + 3072);
        }

        // ---- fill h tiles (fp16): 8 cp16 per thread ----
#pragma unroll
        for (int u = 0; u < 8; u++) {
            int idx = u * 256 + tid;
            int c   = idx >> 7;
            int rem = idx & 127;
            int row = rem >> 3;
            int cc  = rem & 7;
            uint32_t dst = sbase + L_H + (uint32_t)(c * 2048)
                         + SW128((uint32_t)(row * 128 + cc * 16));
            cp16(dst, hf + row * 1024 + c * 64 + cc * 8);
        }
        CP_COMMIT();
        CP_WAIT(0);
        __syncthreads();

        // ---- MMA: W from registers, h via ldsm ----
        float acc[4][4];
#pragma unroll
        for (int i = 0; i < 4; i++)
#pragma unroll
            for (int q = 0; q < 4; q++) acc[i][q] = 0.f;

#pragma unroll
        for (int ci = 0; ci < 2; ci++) {
            int c = 2 * w + ci;
            uint32_t hb = sbase + L_H + (uint32_t)(c * 2048);
#pragma unroll
            for (int kt = 0; kt < 4; kt++) {
                unsigned ah[4];
                uint32_t off = (uint32_t)(a_r * 128)
                             + ((((uint32_t)(kt * 2 + a_cb)) ^ ((uint32_t)a_r & 7)) << 4);
                ldsm_x4(ah, hb + off);
#pragma unroll
                for (int nt = 0; nt < 4; nt++)
                    mma_f16h(acc[nt], ah, &bw[ci][kt][nt >> 1][(nt & 1) * 2]);
            }
        }

        // ---- stage partials ----
#pragma unroll
        for (int nt = 0; nt < 4; nt++) {
            int col = nt * 8 + ec;
            stage[w * 528 + er * 33 + col]           = acc[nt][0];
            stage[w * 528 + er * 33 + col + 1]       = acc[nt][1];
            stage[w * 528 + (er + 8) * 33 + col]     = acc[nt][2];
            stage[w * 528 + (er + 8) * 33 + col + 1] = acc[nt][3];
        }
        __syncthreads();

        // ---- fused reduce + pointwise (128 threads, fast math) ----
        if (tid < 128) {
            float gi = gx0, gf = gx1, gg = gx2, go = gx3;
#pragma unroll
            for (int q = 0; q < 8; q++) {
                const float* sp = stage + q * 528 + pb * 33;
                gi += sp[pc];
                gf += sp[8 + pc];
                gg += sp[16 + pc];
                go += sp[24 + pc];
            }
            float si = 1.f / (1.f + __expf(-gi));
            float sf = 1.f / (1.f + __expf(-gf));
            float tg = 2.f / (1.f + __expf(-2.f * gg)) - 1.f;
            float so = 1.f / (1.f + __expf(-go));
            float cn = sf * c_sm[tid] + si * tg;
            c_sm[tid] = cn;
            float hn = so * (2.f / (1.f + __expf(-2.f * cn)) - 1.f);

            __half h16 = __float2half_rn(hn);
            int sidx = pb * HIDDEN + colp;
            g_hf16[(t + 1) & 1][sidx] = h16;
            g_hist16[(size_t)(pb * SEQ + t) * HIDDEN + colp] = h16;
            if (t == SEQ - 1) hT[sidx] = hn;
        }
        grid_bar(++tgt);
    }
    if (tid < 128)
        cT[pb * HIDDEN + colp] = c_sm[tid];
}

// ------------------------- launch -------------------------
extern "C" void kernel_launch(void* const* d_in, const int* in_sizes, int n_in,
                              void* d_out, int out_size) {
    const int*   x     = (const int*)  d_in[0];
    const float* h0    = (const float*)d_in[1];
    const float* c0    = (const float*)d_in[2];
    const float* emb   = (const float*)d_in[3];
    const float* W_ih0 = (const float*)d_in[4];
    const float* W_hh0 = (const float*)d_in[5];
    const float* b_ih0 = (const float*)d_in[6];
    const float* b_hh0 = (const float*)d_in[7];
    const float* W_ih1 = (const float*)d_in[8];
    const float* W_hh1 = (const float*)d_in[9];
    const float* b_ih1 = (const float*)d_in[10];
    const float* b_hh1 = (const float*)d_in[11];
    const float* fc_W  = (const float*)d_in[12];
    const float* fc_b  = (const float*)d_in[13];

    float* out    = (float*)d_out;
    float* logits = out;
    float* hT     = out + (size_t)MROWS * VOCAB;
    float* cT     = hT + 2 * BATCH * HIDDEN;

    float* p_gatesx;
    __half *p_hist, *p_w16, *p_whh16;
    cudaGetSymbolAddress((void**)&p_gatesx, g_gatesx);
    cudaGetSymbolAddress((void**)&p_hist, g_hist16);
    cudaGetSymbolAddress((void**)&p_w16, g_w16);
    cudaGetSymbolAddress((void**)&p_whh16, g_whh16);

    const int GSM16 = 1024 + 2 * 32768;
    const int GSM256 = 1024 + 2 * 49152;
    cudaFuncSetAttribute(hmma_gemm_f16, cudaFuncAttributeMaxDynamicSharedMemorySize, GSM16);
    cudaFuncSetAttribute(hmma_gemm_w256, cudaFuncAttributeMaxDynamicSharedMemorySize, GSM256);
    cudaFuncSetAttribute(lstm_layer, cudaFuncAttributeMaxDynamicSharedMemorySize, L_DYN);

    const int SH = BATCH * HIDDEN;

    // layer 0
    embed_cvt16<<<MROWS * 64 / 256, 256>>>(x, emb, p_hist);
    cvt_f16<<<GATES * EMBED / 8 / 256, 256>>>(W_ih0, p_w16, GATES * EMBED / 8);
    cvt_f16<<<GATES * HIDDEN / 8 / 256, 256>>>(W_hh0, p_whh16, GATES * HIDDEN / 8);
    hmma_gemm_f16<<<dim3(MROWS / 128, GATES / 128), 256, GSM16>>>(
        p_hist, p_w16, b_ih0, b_hh0, p_gatesx, GATES, EMBED);
    lstm_layer<<<NBLK, 256, L_DYN>>>(p_whh16, p_gatesx, h0, c0, hT, cT);

    // layer 1 (lstm0 wrote fp16 history into g_hist16)
    cvt_f16<<<GATES * HIDDEN / 8 / 256, 256>>>(W_ih1, p_w16, GATES * HIDDEN / 8);
    cvt_f16<<<GATES * HIDDEN / 8 / 256, 256>>>(W_hh1, p_whh16, GATES * HIDDEN / 8);
    hmma_gemm_f16<<<dim3(MROWS / 128, GATES / 128), 256, GSM16>>>(
        p_hist, p_w16, b_ih1, b_hh1, p_gatesx, GATES, HIDDEN);
    lstm_layer<<<NBLK, 256, L_DYN>>>(p_whh16, p_gatesx, h0 + SH, c0 + SH,
                                     hT + SH, cT + SH);

    // FC head: wide 128x256 tile (lstm1 wrote fp16 history into g_hist16)
    cvt_f16<<<VOCAB * HIDDEN / 8 / 256, 256>>>(fc_W, p_w16, VOCAB * HIDDEN / 8);
    hmma_gemm_w256<<<dim3(MROWS / 128, VOCAB / 256), 256, GSM256>>>(
        p_hist, p_w16, fc_b, logits, VOCAB, HIDDEN);
}